// round 11
// baseline (speedup 1.0000x reference)
#include <cuda_runtime.h>
#include <cuda_bf16.h>
#include <math.h>
#include <stdint.h>

#define B_    2
#define S_    2048
#define HID_  2048
#define H_    16
#define D_    128
#define HD_   2048
#define M_    4096
#define NQKV_ 6400
#define SCALE_ 0.08838834764831845f  // D^-0.5

// ---------------- scratch (device globals; no allocation allowed) ----------------
__device__ __align__(256) float g_qkv[M_ * NQKV_];  // q|k|v|fa|ga packed cols
__device__ __align__(256) float g_q[M_ * HD_];
__device__ __align__(256) float g_k[M_ * HD_];
__device__ __align__(256) float g_v[M_ * HD_];
__device__ __align__(256) float g_gf[M_ * HD_];     // holds exp(g_forget) after gsp_k
__device__ __align__(256) float g_gate[M_ * HD_];
__device__ __align__(256) float g_attn[M_ * HD_];
__device__ __align__(256) float g_beta[M_ * H_];

__device__ __align__(256) __nv_bfloat16 g_hsH[M_ * HID_];
__device__ __align__(256) __nv_bfloat16 g_hsL[M_ * HID_];
__device__ __align__(256) __nv_bfloat16 g_WTh[NQKV_ * HID_];  // [Wq|Wk|Wv|Wfa|Wga]^T
__device__ __align__(256) __nv_bfloat16 g_WTl[NQKV_ * HID_];
__device__ __align__(256) __nv_bfloat16 g_fbTh[HD_ * D_];
__device__ __align__(256) __nv_bfloat16 g_fbTl[HD_ * D_];
__device__ __align__(256) __nv_bfloat16 g_gbTh[HD_ * D_];
__device__ __align__(256) __nv_bfloat16 g_gbTl[HD_ * D_];
__device__ __align__(256) __nv_bfloat16 g_WoTh[HID_ * HD_];
__device__ __align__(256) __nv_bfloat16 g_WoTl[HID_ * HD_];
__device__ __align__(256) __nv_bfloat16 g_fgaH[M_ * 256];
__device__ __align__(256) __nv_bfloat16 g_fgaL[M_ * 256];
__device__ __align__(256) __nv_bfloat16 g_noH[M_ * HD_];
__device__ __align__(256) __nv_bfloat16 g_noL[M_ * HD_];

// ---------------- PTX helpers (portable: sm_80+ features only) ----------------
__device__ __forceinline__ uint32_t s2u(const void* p) {
  uint32_t a;
  asm("{ .reg .u64 t; cvta.to.shared.u64 t, %1; cvt.u32.u64 %0, t; }" : "=r"(a) : "l"(p));
  return a;
}
__device__ __forceinline__ void cpa16(uint32_t d, const void* s) {
  asm volatile("cp.async.cg.shared.global [%0], [%1], 16;" :: "r"(d), "l"(s));
}
__device__ __forceinline__ void cpa_commit() { asm volatile("cp.async.commit_group;" ::: "memory"); }
template <int N> __device__ __forceinline__ void cpa_wait() {
  asm volatile("cp.async.wait_group %0;" :: "n"(N) : "memory");
}
__device__ __forceinline__ void ldm4(uint32_t* r, uint32_t a) {
  asm volatile("ldmatrix.sync.aligned.m8n8.x4.shared.b16 {%0,%1,%2,%3}, [%4];"
               : "=r"(r[0]), "=r"(r[1]), "=r"(r[2]), "=r"(r[3]) : "r"(a));
}
__device__ __forceinline__ void mma16816(float* d, const uint32_t* a, const uint32_t* b) {
  asm volatile(
      "mma.sync.aligned.m16n8k16.row.col.f32.bf16.bf16.f32 "
      "{%0,%1,%2,%3}, {%4,%5,%6,%7}, {%8,%9}, {%0,%1,%2,%3};"
      : "+f"(d[0]), "+f"(d[1]), "+f"(d[2]), "+f"(d[3])
      : "r"(a[0]), "r"(a[1]), "r"(a[2]), "r"(a[3]), "r"(b[0]), "r"(b[1]));
}

// ---------------- split-bf16 tensor-core GEMM (measured-best R5 config) ----------------
// C[M,N] = Ahi*Bhi + Ahi*Blo + Alo*Bhi. A:[M,K] K-major bf16, B:[N,K] K-major bf16.
// CTA tile 128x64, BK=32, 8 warps (4x2) each 32x32, 4-stage cp.async, 2 CTAs/SM.
#define GSTAGES 4
#define ATB 8192                // A tile: 128 rows x 64 bytes
#define BTB 4096                // B tile: 64 rows x 64 bytes
#define STB (2 * ATB + 2 * BTB) // Ah|Al|Bh|Bl per stage = 24KB
#define GSMEM_DYN (GSTAGES * STB)  // 96KB

__global__ __launch_bounds__(256, 2) void gemm_tc(
    const __nv_bfloat16* __restrict__ Ah, const __nv_bfloat16* __restrict__ Al, int lda,
    const __nv_bfloat16* __restrict__ Bh, const __nv_bfloat16* __restrict__ Bl, int ldb,
    float* __restrict__ C, int ldc, int K) {
  extern __shared__ __align__(16) char dsm[];
  const uint32_t sb = s2u(dsm);
  const int tid = threadIdx.x;
  const int lane = tid & 31, wid = tid >> 5;
  const int wm = wid >> 1, wn = wid & 1;
  const int m0 = blockIdx.y * 128, n0 = blockIdx.x * 64;
  const int NC = K >> 5;

  float acc[32];
#pragma unroll
  for (int i = 0; i < 32; i++) acc[i] = 0.f;

  auto ld_chunk = [&](int c, int stg) {
    const uint32_t tb = sb + stg * STB;
    const int kb = c * 32;
#pragma unroll
    for (int i = 0; i < 2; i++) {
      const int idx = tid + i * 256;
      const int row = idx >> 2, unit = idx & 3;
      const uint32_t so = (uint32_t)row * 64 + (uint32_t)((unit ^ ((row >> 1) & 3)) << 4);
      const size_t ao = (size_t)(m0 + row) * lda + kb + unit * 8;
      cpa16(tb + so, Ah + ao);
      cpa16(tb + ATB + so, Al + ao);
    }
    {
      const int row = tid >> 2, unit = tid & 3;
      const uint32_t so = (uint32_t)row * 64 + (uint32_t)((unit ^ ((row >> 1) & 3)) << 4);
      const size_t bo = (size_t)(n0 + row) * ldb + kb + unit * 8;
      cpa16(tb + 2 * ATB + so, Bh + bo);
      cpa16(tb + 2 * ATB + BTB + so, Bl + bo);
    }
  };

  for (int s = 0; s < GSTAGES && s < NC; s++) { ld_chunk(s, s); cpa_commit(); }

  for (int c = 0; c < NC; c++) {
    cpa_wait<3>();
    __syncthreads();
    const uint32_t tb = sb + (c & 3) * STB;
#pragma unroll
    for (int kk = 0; kk < 2; kk++) {
      const uint32_t aun = (uint32_t)(((kk * 2 + (lane >> 4)) ^ ((lane >> 1) & 3)) << 4);
      const uint32_t aaddr = tb + (uint32_t)(wm * 32 + (lane & 15)) * 64 + aun;
      const uint32_t bun = (uint32_t)(((kk * 2 + ((lane >> 3) & 1)) ^ ((lane >> 1) & 3)) << 4);
      const uint32_t baddr = tb + 2 * ATB +
          (uint32_t)(wn * 32 + ((lane >> 4) & 1) * 8 + (lane & 7)) * 64 + bun;

      uint32_t af[8], bhf[8], blf[8];
      ldm4(af, aaddr);
      ldm4(af + 4, aaddr + 1024);
      ldm4(bhf, baddr);
      ldm4(bhf + 4, baddr + 1024);
      ldm4(blf, baddr + BTB);
      ldm4(blf + 4, baddr + BTB + 1024);
#pragma unroll
      for (int mt = 0; mt < 2; mt++)
#pragma unroll
        for (int nt = 0; nt < 4; nt++)
          mma16816(&acc[(mt * 4 + nt) * 4], af + mt * 4, bhf + nt * 2);
#pragma unroll
      for (int mt = 0; mt < 2; mt++)
#pragma unroll
        for (int nt = 0; nt < 4; nt++)
          mma16816(&acc[(mt * 4 + nt) * 4], af + mt * 4, blf + nt * 2);
      // A-lo reuses A-hi registers
      ldm4(af, aaddr + ATB);
      ldm4(af + 4, aaddr + ATB + 1024);
#pragma unroll
      for (int mt = 0; mt < 2; mt++)
#pragma unroll
        for (int nt = 0; nt < 4; nt++)
          mma16816(&acc[(mt * 4 + nt) * 4], af + mt * 4, bhf + nt * 2);
    }
    if (c + 3 < NC) { ld_chunk(c + 3, (c + 3) & 3); cpa_commit(); }
  }

  const int rbase = m0 + wm * 32 + (lane >> 2);
  const int cbase = n0 + wn * 32 + (lane & 3) * 2;
#pragma unroll
  for (int mt = 0; mt < 2; mt++) {
#pragma unroll
    for (int nt = 0; nt < 4; nt++) {
      const float* a4 = &acc[(mt * 4 + nt) * 4];
      *(float2*)(C + (size_t)(rbase + mt * 16) * ldc + cbase + nt * 8) =
          make_float2(a4[0], a4[1]);
      *(float2*)(C + (size_t)(rbase + mt * 16 + 8) * ldc + cbase + nt * 8) =
          make_float2(a4[2], a4[3]);
    }
  }
}

// ---------------- fp32 -> bf16 hi/lo split ----------------
__device__ __forceinline__ void split1(float x, unsigned short& h, unsigned short& l) {
  __nv_bfloat16 hb = __float2bfloat16_rn(x);
  float r = x - __bfloat162float(hb);
  __nv_bfloat16 lb = __float2bfloat16_rn(r);
  h = *reinterpret_cast<unsigned short*>(&hb);
  l = *reinterpret_cast<unsigned short*>(&lb);
}

__global__ void split4_k(const float4* __restrict__ src, __nv_bfloat16* __restrict__ dh,
                         __nv_bfloat16* __restrict__ dl) {
  int i = blockIdx.x * blockDim.x + threadIdx.x;
  float4 v = src[i];
  ushort4 h, l;
  split1(v.x, h.x, l.x);
  split1(v.y, h.y, l.y);
  split1(v.z, h.z, l.z);
  split1(v.w, h.w, l.w);
  ((ushort4*)dh)[i] = h;
  ((ushort4*)dl)[i] = l;
}

__global__ void split_fga_k() {  // cols [6144,6400) of g_qkv -> compact [4096,256]
  int i = blockIdx.x * blockDim.x + threadIdx.x;  // over 4096*64
  int row = i >> 6, c4 = i & 63;
  float4 v = *(const float4*)&g_qkv[(size_t)row * NQKV_ + 6144 + c4 * 4];
  ushort4 h, l;
  split1(v.x, h.x, l.x);
  split1(v.y, h.y, l.y);
  split1(v.z, h.z, l.z);
  split1(v.w, h.w, l.w);
  *(ushort4*)&g_fgaH[(size_t)row * 256 + c4 * 4] = h;
  *(ushort4*)&g_fgaL[(size_t)row * 256 + c4 * 4] = l;
}

// ---------------- weight transpose + split: W[K,Nsrc] -> T[n_off+n][k] ----------------
__global__ __launch_bounds__(256) void wtrans_k(const float* __restrict__ src,
                                                __nv_bfloat16* __restrict__ dh,
                                                __nv_bfloat16* __restrict__ dl,
                                                int n_off, int Nsrc, int Kd) {
  __shared__ float t[32][33];
  int tx = threadIdx.x & 31, ty = threadIdx.x >> 5;
  int n0 = blockIdx.x * 32, k0 = blockIdx.y * 32;
#pragma unroll
  for (int i = 0; i < 4; i++) {
    int k = k0 + ty + i * 8;
    t[ty + i * 8][tx] = src[(size_t)k * Nsrc + n0 + tx];
  }
  __syncthreads();
#pragma unroll
  for (int i = 0; i < 4; i++) {
    int n = n0 + ty + i * 8;
    float v = t[tx][ty + i * 8];
    unsigned short h, l;
    split1(v, h, l);
    size_t o = (size_t)(n_off + n) * Kd + k0 + tx;
    *reinterpret_cast<unsigned short*>(&dh[o]) = h;
    *reinterpret_cast<unsigned short*>(&dl[o]) = l;
  }
}

// ---------------- l2 norm over q,k parts of g_qkv (cols [0,4096), groups of 128) ----------------
__global__ __launch_bounds__(128) void l2q_k() {
  int g = blockIdx.x * 4 + (threadIdx.x >> 5);
  int lane = threadIdx.x & 31;
  int row = g >> 5, cg = g & 31;
  float* p = g_qkv + (size_t)row * NQKV_ + cg * 128;
  float v0 = p[lane], v1 = p[lane + 32], v2 = p[lane + 64], v3 = p[lane + 96];
  float s = v0 * v0 + v1 * v1 + v2 * v2 + v3 * v3;
#pragma unroll
  for (int o = 16; o; o >>= 1) s += __shfl_xor_sync(0xffffffffu, s, o);
  float r = rsqrtf(s + 1e-6f);
  p[lane] = v0 * r;
  p[lane + 32] = v1 * r;
  p[lane + 64] = v2 * r;
  p[lane + 96] = v3 * r;
}

// ---------------- causal depthwise conv (K=4) + SiLU, src stride NQKV_ ----------------
__global__ void conv2_k(const float* __restrict__ src, const float* __restrict__ w,
                        float* __restrict__ dst) {
  int idx = blockIdx.x * blockDim.x + threadIdx.x;
  int c = idx & (HD_ - 1);
  int bs = idx >> 11;
  int s = bs & (S_ - 1);
  float acc = 0.f;
#pragma unroll
  for (int j = 0; j < 4; j++) {
    int sp = s - 3 + j;
    if (sp >= 0) acc += src[(size_t)(bs - 3 + j) * NQKV_ + c] * w[j * HD_ + c];
  }
  dst[idx] = acc / (1.f + __expf(-acc));
}

// ---------------- beta = sigmoid(hs @ Wb), N=16 ----------------
__global__ __launch_bounds__(128) void beta_k(const float* __restrict__ hs,
                                              const float* __restrict__ Wb) {
  __shared__ float part[16][128];
  int m = blockIdx.x, tid = threadIdx.x;
  float acc[16];
#pragma unroll
  for (int h = 0; h < 16; h++) acc[h] = 0.f;
  const float* hp = hs + (size_t)m * HID_;
  for (int d = tid; d < HID_; d += 128) {
    float hv = hp[d];
    const float* wr = Wb + (size_t)d * 16;
#pragma unroll
    for (int h = 0; h < 16; h++) acc[h] += hv * wr[h];
  }
#pragma unroll
  for (int h = 0; h < 16; h++) part[h][tid] = acc[h];
  __syncthreads();
  for (int o = 64; o > 0; o >>= 1) {
    if (tid < o) {
#pragma unroll
      for (int h = 0; h < 16; h++) part[h][tid] += part[h][tid + o];
    }
    __syncthreads();
  }
  if (tid < 16) {
    float x = part[tid][0];
    g_beta[(size_t)m * 16 + tid] = 1.f / (1.f + __expf(-x));
  }
}

// ---------------- forget gate: exp(-exp(A_log[h]) * softplus(glin + dt_bias)) ----------------
__global__ void gsp_k(const float* __restrict__ A_log, const float* __restrict__ dt_bias) {
  int idx = blockIdx.x * blockDim.x + threadIdx.x;
  int c = idx & (HD_ - 1);
  int h = c >> 7;
  float x = g_gf[idx] + dt_bias[c];
  float sp = (x > 20.f) ? x : log1pf(__expf(x));
  g_gf[idx] = __expf(-expf(A_log[h]) * sp);  // store exp(g) directly
}

// ---------------- delta rule scan (warp = k-slice; broadcast LDS) — R5-measured-best ----------------
// grid (32, 4): x = b*16+h, y = col group (32 cols). 128 thr = 4 warps (k-slices) x 32 lanes (cols).
__global__ __launch_bounds__(128) void delta_k() {
  const int bh = blockIdx.x;
  const int b = bh >> 4, h = bh & 15;
  const int grp = blockIdx.y;
  const int tid = threadIdx.x;
  const int w = tid >> 5;    // k-slice [32w, 32w+32)
  const int l = tid & 31;    // column within group
  const int jcol = grp * 32 + l;

  __shared__ float4 stg[2][128];   // element d: {k, q*sc, exp(g), 0}
  __shared__ float vst[2][128];
  __shared__ float epart[160];     // [l*5 + w]
  __shared__ float opart[160];

  float Sacc[32], kk[32], qq[32];
#pragma unroll
  for (int i = 0; i < 32; i++) Sacc[i] = 0.f;

  const size_t base = ((size_t)b * S_ * H_ + h) * D_;
  const float* Qp = g_q + base;
  const float* Kp = g_k + base;
  const float* Vp = g_v + base;
  const float* Gp = g_gf + base;  // exp(g) precomputed
  const float* Bp = g_beta + (size_t)b * S_ * H_ + h;
  float* Op = g_attn + base;

  // prefetch t = 0 and stage it
  float kv = Kp[tid], qv = Qp[tid], gv = Gp[tid], vv = Vp[tid], bt = Bp[0];
  stg[0][tid] = make_float4(kv, qv * SCALE_, gv, 0.f);
  vst[0][tid] = vv;
  int buf = 0;
  __syncthreads();

  for (int t = 0; t < S_; t++) {
    float btc = bt;
    if (t + 1 < S_) {  // prefetch next step into regs (overlaps compute)
      size_t o = (size_t)(t + 1) * HD_;
      kv = Kp[o + tid]; qv = Qp[o + tid]; gv = Gp[o + tid]; vv = Vp[o + tid];
      bt = Bp[(size_t)(t + 1) * H_];
    }

    // phase 1: decay + k.S partial (warp-uniform broadcast reads)
    const float4* st = stg[buf] + w * 32;
    float e = 0.f;
#pragma unroll
    for (int ii = 0; ii < 32; ii++) {
      float4 a = st[ii];
      float sv = Sacc[ii] * a.z;
      Sacc[ii] = sv;
      kk[ii] = a.x;
      qq[ii] = a.y;
      e += a.x * sv;
    }
    epart[l * 5 + w] = e;
    float vj = vst[buf][jcol];
    __syncthreads();

    float er = (epart[l * 5 + 0] + epart[l * 5 + 1]) +
               (epart[l * 5 + 2] + epart[l * 5 + 3]);
    float be = btc * (vj - er);

    // phase 2: rank-1 update + q.S partial (no LDS: k,q cached)
    float o2 = 0.f;
#pragma unroll
    for (int ii = 0; ii < 32; ii++) {
      float sv = Sacc[ii] + kk[ii] * be;
      Sacc[ii] = sv;
      o2 += qq[ii] * sv;
    }
    opart[l * 5 + w] = o2;

    // stage t+1 while here
    stg[buf ^ 1][tid] = make_float4(kv, qv * SCALE_, gv, 0.f);
    vst[buf ^ 1][tid] = vv;
    __syncthreads();

    if (w == 0) {
      float ov = (opart[l * 5 + 0] + opart[l * 5 + 1]) +
                 (opart[l * 5 + 2] + opart[l * 5 + 3]);
      Op[(size_t)t * HD_ + jcol] = ov;
    }
    buf ^= 1;
  }
}

// ---------------- RMSNorm * sigmoid gate -> bf16 hi/lo (fused split) ----------------
__global__ __launch_bounds__(128) void rmsgate_k(const float* __restrict__ rms_scale) {
  int row = blockIdx.x * 4 + (threadIdx.x >> 5);
  int lane = threadIdx.x & 31;
  const float* ap = g_attn + (size_t)row * 128;
  const float* gp = g_gate + (size_t)row * 128;
  float a0 = ap[lane], a1 = ap[lane + 32], a2 = ap[lane + 64], a3 = ap[lane + 96];
  float s = a0 * a0 + a1 * a1 + a2 * a2 + a3 * a3;
#pragma unroll
  for (int o = 16; o; o >>= 1) s += __shfl_xor_sync(0xffffffffu, s, o);
  float rn = rsqrtf(s * (1.f / 128.f) + 1e-5f);
#pragma unroll
  for (int j = 0; j < 4; j++) {
    int d = lane + 32 * j;
    float a = (j == 0) ? a0 : (j == 1) ? a1 : (j == 2) ? a2 : a3;
    float gt = gp[d];
    float o = a * rn * rms_scale[d] * (1.f / (1.f + __expf(-gt)));
    unsigned short hh, ll;
    split1(o, hh, ll);
    *reinterpret_cast<unsigned short*>(&g_noH[(size_t)row * 128 + d]) = hh;
    *reinterpret_cast<unsigned short*>(&g_noL[(size_t)row * 128 + d]) = ll;
  }
}

// ---------------- launch ----------------
extern "C" void kernel_launch(void* const* d_in, const int* in_sizes, int n_in,
                              void* d_out, int out_size) {
  const float* hs      = (const float*)d_in[0];
  const float* Wq      = (const float*)d_in[1];
  const float* Wk      = (const float*)d_in[2];
  const float* Wv      = (const float*)d_in[3];
  const float* conv_q  = (const float*)d_in[4];
  const float* conv_k  = (const float*)d_in[5];
  const float* conv_v  = (const float*)d_in[6];
  const float* Wb      = (const float*)d_in[7];
  const float* Wfa     = (const float*)d_in[8];
  const float* Wfb     = (const float*)d_in[9];
  const float* Wga     = (const float*)d_in[10];
  const float* Wgb     = (const float*)d_in[11];
  const float* A_log   = (const float*)d_in[12];
  const float* dt_bias = (const float*)d_in[13];
  const float* rmssc   = (const float*)d_in[14];
  const float* Wo      = (const float*)d_in[15];
  float* out = (float*)d_out;

  cudaFuncSetAttribute(gemm_tc, cudaFuncAttributeMaxDynamicSharedMemorySize, GSMEM_DYN);

  // lazy stream/event creation: happens on the FIRST (non-captured) correctness
  // call only, so nothing is created during graph capture.
  static cudaStream_t s2 = nullptr;
  static cudaEvent_t evS = nullptr, evA = nullptr, evB = nullptr, evC = nullptr, evD = nullptr;
  if (s2 == nullptr) {
    cudaStreamCreateWithFlags(&s2, cudaStreamNonBlocking);
    cudaEventCreateWithFlags(&evS, cudaEventDisableTiming);
    cudaEventCreateWithFlags(&evA, cudaEventDisableTiming);
    cudaEventCreateWithFlags(&evB, cudaEventDisableTiming);
    cudaEventCreateWithFlags(&evC, cudaEventDisableTiming);
    cudaEventCreateWithFlags(&evD, cudaEventDisableTiming);
  }

  float *qkv, *gf, *gate, *qb, *kb, *vb;
  __nv_bfloat16 *hsH, *hsL, *WTh, *WTl, *fbTh, *fbTl, *gbTh, *gbTl, *WoTh, *WoTl;
  __nv_bfloat16 *fgaH, *fgaL, *noH, *noL;
  cudaGetSymbolAddress((void**)&qkv, g_qkv);
  cudaGetSymbolAddress((void**)&gf, g_gf);
  cudaGetSymbolAddress((void**)&gate, g_gate);
  cudaGetSymbolAddress((void**)&qb, g_q);
  cudaGetSymbolAddress((void**)&kb, g_k);
  cudaGetSymbolAddress((void**)&vb, g_v);
  cudaGetSymbolAddress((void**)&hsH, g_hsH);
  cudaGetSymbolAddress((void**)&hsL, g_hsL);
  cudaGetSymbolAddress((void**)&WTh, g_WTh);
  cudaGetSymbolAddress((void**)&WTl, g_WTl);
  cudaGetSymbolAddress((void**)&fbTh, g_fbTh);
  cudaGetSymbolAddress((void**)&fbTl, g_fbTl);
  cudaGetSymbolAddress((void**)&gbTh, g_gbTh);
  cudaGetSymbolAddress((void**)&gbTl, g_gbTl);
  cudaGetSymbolAddress((void**)&WoTh, g_WoTh);
  cudaGetSymbolAddress((void**)&WoTl, g_WoTl);
  cudaGetSymbolAddress((void**)&fgaH, g_fgaH);
  cudaGetSymbolAddress((void**)&fgaL, g_fgaL);
  cudaGetSymbolAddress((void**)&noH, g_noH);
  cudaGetSymbolAddress((void**)&noL, g_noL);

  const int nEl = M_ * HD_ / 256;

  // fork s2 off the main (captured) stream
  cudaEventRecord(evS, 0);
  cudaStreamWaitEvent(s2, evS, 0);

  // s2: weight prep pipeline (independent of activations)
  wtrans_k<<<dim3(64, 64), 256, 0, s2>>>(Wq, WTh, WTl, 0, 2048, 2048);
  wtrans_k<<<dim3(64, 64), 256, 0, s2>>>(Wk, WTh, WTl, 2048, 2048, 2048);
  wtrans_k<<<dim3(64, 64), 256, 0, s2>>>(Wv, WTh, WTl, 4096, 2048, 2048);
  wtrans_k<<<dim3(4, 64), 256, 0, s2>>>(Wfa, WTh, WTl, 6144, 128, 2048);
  wtrans_k<<<dim3(4, 64), 256, 0, s2>>>(Wga, WTh, WTl, 6272, 128, 2048);
  cudaEventRecord(evA, s2);                                  // QKV GEMM B operands ready
  wtrans_k<<<dim3(64, 4), 256, 0, s2>>>(Wfb, fbTh, fbTl, 0, 2048, 128);
  wtrans_k<<<dim3(64, 4), 256, 0, s2>>>(Wgb, gbTh, gbTl, 0, 2048, 128);
  cudaEventRecord(evB, s2);                                  // gate GEMM B operands ready
  beta_k<<<M_, 128, 0, s2>>>(hs, Wb);
  cudaEventRecord(evC, s2);                                  // beta ready (for scan)
  wtrans_k<<<dim3(64, 64), 256, 0, s2>>>(Wo, WoTh, WoTl, 0, 2048, 2048);
  cudaEventRecord(evD, s2);                                  // Wo ready (also joins s2)

  // main stream: activation pipeline
  split4_k<<<M_ * HID_ / 4 / 256, 256>>>((const float4*)hs, hsH, hsL);
  cudaStreamWaitEvent(0, evA, 0);
  gemm_tc<<<dim3(100, 32), 256, GSMEM_DYN>>>(hsH, hsL, 2048, WTh, WTl, 2048, qkv, NQKV_, 2048);

  split_fga_k<<<M_ * 64 / 256, 256>>>();
  cudaStreamWaitEvent(0, evB, 0);
  gemm_tc<<<dim3(32, 32), 256, GSMEM_DYN>>>(fgaH, fgaL, 256, fbTh, fbTl, 128, gf, 2048, 128);
  gemm_tc<<<dim3(32, 32), 256, GSMEM_DYN>>>(fgaH + 128, fgaL + 128, 256, gbTh, gbTl, 128, gate, 2048, 128);
  gsp_k<<<nEl, 256>>>(A_log, dt_bias);

  l2q_k<<<32768, 128>>>();
  conv2_k<<<nEl, 256>>>(qkv + 0, conv_q, qb);
  conv2_k<<<nEl, 256>>>(qkv + 2048, conv_k, kb);
  conv2_k<<<nEl, 256>>>(qkv + 4096, conv_v, vb);

  cudaStreamWaitEvent(0, evC, 0);
  delta_k<<<dim3(B_ * H_, 4), 128>>>();

  rmsgate_k<<<M_ * H_ / 4, 128>>>(rmssc);
  cudaStreamWaitEvent(0, evD, 0);
  gemm_tc<<<dim3(32, 32), 256, GSMEM_DYN>>>(noH, noL, 2048, WoTh, WoTl, 2048, out, 2048, 2048);
}

// round 13
// speedup vs baseline: 1.1224x; 1.1224x over previous
#include <cuda_runtime.h>
#include <cuda_bf16.h>
#include <math.h>
#include <stdint.h>

#define B_    2
#define S_    2048
#define HID_  2048
#define H_    16
#define D_    128
#define HD_   2048
#define M_    4096
#define NQKV_ 6400
#define SCALE_ 0.08838834764831845f  // D^-0.5

// ---------------- scratch (device globals; no allocation allowed) ----------------
__device__ __align__(256) float g_qkv[M_ * NQKV_];  // q|k|v|fa|ga packed cols
__device__ __align__(256) float g_q[M_ * HD_];
__device__ __align__(256) float g_k[M_ * HD_];
__device__ __align__(256) float g_v[M_ * HD_];
__device__ __align__(256) float g_gf[M_ * HD_];     // holds exp(g_forget) after gsp_k
__device__ __align__(256) float g_gate[M_ * HD_];
__device__ __align__(256) float g_attn[M_ * HD_];
__device__ __align__(256) float g_beta[M_ * H_];

__device__ __align__(256) __nv_bfloat16 g_hsH[M_ * HID_];
__device__ __align__(256) __nv_bfloat16 g_hsL[M_ * HID_];
__device__ __align__(256) __nv_bfloat16 g_WTh[NQKV_ * HID_];  // [Wq|Wk|Wv|Wfa|Wga]^T
__device__ __align__(256) __nv_bfloat16 g_WTl[NQKV_ * HID_];
__device__ __align__(256) __nv_bfloat16 g_fbTh[HD_ * D_];
__device__ __align__(256) __nv_bfloat16 g_fbTl[HD_ * D_];
__device__ __align__(256) __nv_bfloat16 g_gbTh[HD_ * D_];
__device__ __align__(256) __nv_bfloat16 g_gbTl[HD_ * D_];
__device__ __align__(256) __nv_bfloat16 g_WoTh[HID_ * HD_];
__device__ __align__(256) __nv_bfloat16 g_WoTl[HID_ * HD_];
__device__ __align__(256) __nv_bfloat16 g_fgaH[M_ * 256];
__device__ __align__(256) __nv_bfloat16 g_fgaL[M_ * 256];
__device__ __align__(256) __nv_bfloat16 g_noH[M_ * HD_];
__device__ __align__(256) __nv_bfloat16 g_noL[M_ * HD_];

// ---------------- PTX helpers (portable: sm_80+ features only) ----------------
__device__ __forceinline__ uint32_t s2u(const void* p) {
  uint32_t a;
  asm("{ .reg .u64 t; cvta.to.shared.u64 t, %1; cvt.u32.u64 %0, t; }" : "=r"(a) : "l"(p));
  return a;
}
__device__ __forceinline__ void cpa16(uint32_t d, const void* s) {
  asm volatile("cp.async.cg.shared.global [%0], [%1], 16;" :: "r"(d), "l"(s));
}
__device__ __forceinline__ void cpa_commit() { asm volatile("cp.async.commit_group;" ::: "memory"); }
template <int N> __device__ __forceinline__ void cpa_wait() {
  asm volatile("cp.async.wait_group %0;" :: "n"(N) : "memory");
}
__device__ __forceinline__ void ldm4(uint32_t* r, uint32_t a) {
  asm volatile("ldmatrix.sync.aligned.m8n8.x4.shared.b16 {%0,%1,%2,%3}, [%4];"
               : "=r"(r[0]), "=r"(r[1]), "=r"(r[2]), "=r"(r[3]) : "r"(a));
}
__device__ __forceinline__ void mma16816(float* d, const uint32_t* a, const uint32_t* b) {
  asm volatile(
      "mma.sync.aligned.m16n8k16.row.col.f32.bf16.bf16.f32 "
      "{%0,%1,%2,%3}, {%4,%5,%6,%7}, {%8,%9}, {%0,%1,%2,%3};"
      : "+f"(d[0]), "+f"(d[1]), "+f"(d[2]), "+f"(d[3])
      : "r"(a[0]), "r"(a[1]), "r"(a[2]), "r"(a[3]), "r"(b[0]), "r"(b[1]));
}

// ---------------- split-bf16 tensor-core GEMM (measured-best R5 config) ----------------
// C[M,N] = Ahi*Bhi + Ahi*Blo + Alo*Bhi. A:[M,K] K-major bf16, B:[N,K] K-major bf16.
// CTA tile 128x64, BK=32, 8 warps (4x2) each 32x32, 4-stage cp.async, 2 CTAs/SM.
#define GSTAGES 4
#define ATB 8192                // A tile: 128 rows x 64 bytes
#define BTB 4096                // B tile: 64 rows x 64 bytes
#define STB (2 * ATB + 2 * BTB) // Ah|Al|Bh|Bl per stage = 24KB
#define GSMEM_DYN (GSTAGES * STB)  // 96KB

__global__ __launch_bounds__(256, 2) void gemm_tc(
    const __nv_bfloat16* __restrict__ Ah, const __nv_bfloat16* __restrict__ Al, int lda,
    const __nv_bfloat16* __restrict__ Bh, const __nv_bfloat16* __restrict__ Bl, int ldb,
    float* __restrict__ C, int ldc, int K) {
  extern __shared__ __align__(16) char dsm[];
  const uint32_t sb = s2u(dsm);
  const int tid = threadIdx.x;
  const int lane = tid & 31, wid = tid >> 5;
  const int wm = wid >> 1, wn = wid & 1;
  const int m0 = blockIdx.y * 128, n0 = blockIdx.x * 64;
  const int NC = K >> 5;

  float acc[32];
#pragma unroll
  for (int i = 0; i < 32; i++) acc[i] = 0.f;

  auto ld_chunk = [&](int c, int stg) {
    const uint32_t tb = sb + stg * STB;
    const int kb = c * 32;
#pragma unroll
    for (int i = 0; i < 2; i++) {
      const int idx = tid + i * 256;
      const int row = idx >> 2, unit = idx & 3;
      const uint32_t so = (uint32_t)row * 64 + (uint32_t)((unit ^ ((row >> 1) & 3)) << 4);
      const size_t ao = (size_t)(m0 + row) * lda + kb + unit * 8;
      cpa16(tb + so, Ah + ao);
      cpa16(tb + ATB + so, Al + ao);
    }
    {
      const int row = tid >> 2, unit = tid & 3;
      const uint32_t so = (uint32_t)row * 64 + (uint32_t)((unit ^ ((row >> 1) & 3)) << 4);
      const size_t bo = (size_t)(n0 + row) * ldb + kb + unit * 8;
      cpa16(tb + 2 * ATB + so, Bh + bo);
      cpa16(tb + 2 * ATB + BTB + so, Bl + bo);
    }
  };

  for (int s = 0; s < GSTAGES && s < NC; s++) { ld_chunk(s, s); cpa_commit(); }

  for (int c = 0; c < NC; c++) {
    cpa_wait<3>();
    __syncthreads();
    const uint32_t tb = sb + (c & 3) * STB;
#pragma unroll
    for (int kk = 0; kk < 2; kk++) {
      const uint32_t aun = (uint32_t)(((kk * 2 + (lane >> 4)) ^ ((lane >> 1) & 3)) << 4);
      const uint32_t aaddr = tb + (uint32_t)(wm * 32 + (lane & 15)) * 64 + aun;
      const uint32_t bun = (uint32_t)(((kk * 2 + ((lane >> 3) & 1)) ^ ((lane >> 1) & 3)) << 4);
      const uint32_t baddr = tb + 2 * ATB +
          (uint32_t)(wn * 32 + ((lane >> 4) & 1) * 8 + (lane & 7)) * 64 + bun;

      uint32_t af[8], bhf[8], blf[8];
      ldm4(af, aaddr);
      ldm4(af + 4, aaddr + 1024);
      ldm4(bhf, baddr);
      ldm4(bhf + 4, baddr + 1024);
      ldm4(blf, baddr + BTB);
      ldm4(blf + 4, baddr + BTB + 1024);
#pragma unroll
      for (int mt = 0; mt < 2; mt++)
#pragma unroll
        for (int nt = 0; nt < 4; nt++)
          mma16816(&acc[(mt * 4 + nt) * 4], af + mt * 4, bhf + nt * 2);
#pragma unroll
      for (int mt = 0; mt < 2; mt++)
#pragma unroll
        for (int nt = 0; nt < 4; nt++)
          mma16816(&acc[(mt * 4 + nt) * 4], af + mt * 4, blf + nt * 2);
      // A-lo reuses A-hi registers
      ldm4(af, aaddr + ATB);
      ldm4(af + 4, aaddr + ATB + 1024);
#pragma unroll
      for (int mt = 0; mt < 2; mt++)
#pragma unroll
        for (int nt = 0; nt < 4; nt++)
          mma16816(&acc[(mt * 4 + nt) * 4], af + mt * 4, bhf + nt * 2);
    }
    if (c + 3 < NC) { ld_chunk(c + 3, (c + 3) & 3); cpa_commit(); }
  }

  const int rbase = m0 + wm * 32 + (lane >> 2);
  const int cbase = n0 + wn * 32 + (lane & 3) * 2;
#pragma unroll
  for (int mt = 0; mt < 2; mt++) {
#pragma unroll
    for (int nt = 0; nt < 4; nt++) {
      const float* a4 = &acc[(mt * 4 + nt) * 4];
      *(float2*)(C + (size_t)(rbase + mt * 16) * ldc + cbase + nt * 8) =
          make_float2(a4[0], a4[1]);
      *(float2*)(C + (size_t)(rbase + mt * 16 + 8) * ldc + cbase + nt * 8) =
          make_float2(a4[2], a4[3]);
    }
  }
}

// ---------------- fp32 -> bf16 hi/lo split ----------------
__device__ __forceinline__ void split1(float x, unsigned short& h, unsigned short& l) {
  __nv_bfloat16 hb = __float2bfloat16_rn(x);
  float r = x - __bfloat162float(hb);
  __nv_bfloat16 lb = __float2bfloat16_rn(r);
  h = *reinterpret_cast<unsigned short*>(&hb);
  l = *reinterpret_cast<unsigned short*>(&lb);
}

__global__ void split4_k(const float4* __restrict__ src, __nv_bfloat16* __restrict__ dh,
                         __nv_bfloat16* __restrict__ dl) {
  int i = blockIdx.x * blockDim.x + threadIdx.x;
  float4 v = src[i];
  ushort4 h, l;
  split1(v.x, h.x, l.x);
  split1(v.y, h.y, l.y);
  split1(v.z, h.z, l.z);
  split1(v.w, h.w, l.w);
  ((ushort4*)dh)[i] = h;
  ((ushort4*)dl)[i] = l;
}

__global__ void split_fga_k() {  // cols [6144,6400) of g_qkv -> compact [4096,256]
  int i = blockIdx.x * blockDim.x + threadIdx.x;  // over 4096*64
  int row = i >> 6, c4 = i & 63;
  float4 v = *(const float4*)&g_qkv[(size_t)row * NQKV_ + 6144 + c4 * 4];
  ushort4 h, l;
  split1(v.x, h.x, l.x);
  split1(v.y, h.y, l.y);
  split1(v.z, h.z, l.z);
  split1(v.w, h.w, l.w);
  *(ushort4*)&g_fgaH[(size_t)row * 256 + c4 * 4] = h;
  *(ushort4*)&g_fgaL[(size_t)row * 256 + c4 * 4] = l;
}

// ---------------- weight transpose + split: W[K,Nsrc] -> T[n_off+n][k] ----------------
__global__ __launch_bounds__(256) void wtrans_k(const float* __restrict__ src,
                                                __nv_bfloat16* __restrict__ dh,
                                                __nv_bfloat16* __restrict__ dl,
                                                int n_off, int Nsrc, int Kd) {
  __shared__ float t[32][33];
  int tx = threadIdx.x & 31, ty = threadIdx.x >> 5;
  int n0 = blockIdx.x * 32, k0 = blockIdx.y * 32;
#pragma unroll
  for (int i = 0; i < 4; i++) {
    int k = k0 + ty + i * 8;
    t[ty + i * 8][tx] = src[(size_t)k * Nsrc + n0 + tx];
  }
  __syncthreads();
#pragma unroll
  for (int i = 0; i < 4; i++) {
    int n = n0 + ty + i * 8;
    float v = t[tx][ty + i * 8];
    unsigned short h, l;
    split1(v, h, l);
    size_t o = (size_t)(n_off + n) * Kd + k0 + tx;
    *reinterpret_cast<unsigned short*>(&dh[o]) = h;
    *reinterpret_cast<unsigned short*>(&dl[o]) = l;
  }
}

// ---------------- l2 norm over q,k parts of g_qkv (cols [0,4096), groups of 128) ----------------
__global__ __launch_bounds__(128) void l2q_k() {
  int g = blockIdx.x * 4 + (threadIdx.x >> 5);
  int lane = threadIdx.x & 31;
  int row = g >> 5, cg = g & 31;
  float* p = g_qkv + (size_t)row * NQKV_ + cg * 128;
  float v0 = p[lane], v1 = p[lane + 32], v2 = p[lane + 64], v3 = p[lane + 96];
  float s = v0 * v0 + v1 * v1 + v2 * v2 + v3 * v3;
#pragma unroll
  for (int o = 16; o; o >>= 1) s += __shfl_xor_sync(0xffffffffu, s, o);
  float r = rsqrtf(s + 1e-6f);
  p[lane] = v0 * r;
  p[lane + 32] = v1 * r;
  p[lane + 64] = v2 * r;
  p[lane + 96] = v3 * r;
}

// ---------------- causal depthwise conv (K=4) + SiLU, src stride NQKV_ ----------------
__global__ void conv2_k(const float* __restrict__ src, const float* __restrict__ w,
                        float* __restrict__ dst) {
  int idx = blockIdx.x * blockDim.x + threadIdx.x;
  int c = idx & (HD_ - 1);
  int bs = idx >> 11;
  int s = bs & (S_ - 1);
  float acc = 0.f;
#pragma unroll
  for (int j = 0; j < 4; j++) {
    int sp = s - 3 + j;
    if (sp >= 0) acc += src[(size_t)(bs - 3 + j) * NQKV_ + c] * w[j * HD_ + c];
  }
  dst[idx] = acc / (1.f + __expf(-acc));
}

// ---------------- beta = sigmoid(hs @ Wb), N=16 ----------------
__global__ __launch_bounds__(128) void beta_k(const float* __restrict__ hs,
                                              const float* __restrict__ Wb) {
  __shared__ float part[16][128];
  int m = blockIdx.x, tid = threadIdx.x;
  float acc[16];
#pragma unroll
  for (int h = 0; h < 16; h++) acc[h] = 0.f;
  const float* hp = hs + (size_t)m * HID_;
  for (int d = tid; d < HID_; d += 128) {
    float hv = hp[d];
    const float* wr = Wb + (size_t)d * 16;
#pragma unroll
    for (int h = 0; h < 16; h++) acc[h] += hv * wr[h];
  }
#pragma unroll
  for (int h = 0; h < 16; h++) part[h][tid] = acc[h];
  __syncthreads();
  for (int o = 64; o > 0; o >>= 1) {
    if (tid < o) {
#pragma unroll
      for (int h = 0; h < 16; h++) part[h][tid] += part[h][tid + o];
    }
    __syncthreads();
  }
  if (tid < 16) {
    float x = part[tid][0];
    g_beta[(size_t)m * 16 + tid] = 1.f / (1.f + __expf(-x));
  }
}

// ---------------- forget gate: exp(-exp(A_log[h]) * softplus(glin + dt_bias)) ----------------
__global__ void gsp_k(const float* __restrict__ A_log, const float* __restrict__ dt_bias) {
  int idx = blockIdx.x * blockDim.x + threadIdx.x;
  int c = idx & (HD_ - 1);
  int h = c >> 7;
  float x = g_gf[idx] + dt_bias[c];
  float sp = (x > 20.f) ? x : log1pf(__expf(x));
  g_gf[idx] = __expf(-expf(A_log[h]) * sp);  // store exp(g) directly
}

// ---------------- delta rule scan (8 warps = 8 k-slices of 16; broadcast LDS) ----------------
// grid (32, 4): x = b*16+h, y = col group (32 cols). 256 thr = 8 warps x 32 lanes (cols).
__global__ __launch_bounds__(256) void delta_k() {
  const int bh = blockIdx.x;
  const int b = bh >> 4, h = bh & 15;
  const int grp = blockIdx.y;
  const int tid = threadIdx.x;
  const int w = tid >> 5;    // k-slice [16w, 16w+16)
  const int l = tid & 31;    // column within group
  const int jcol = grp * 32 + l;

  __shared__ float4 stg[2][128];   // element d: {k, q*sc, exp(g), 0}
  __shared__ float vst[2][128];
  __shared__ float epart[288];     // [l*9 + w]
  __shared__ float opart[288];

  float Sacc[16], kk[16], qq[16];
#pragma unroll
  for (int i = 0; i < 16; i++) Sacc[i] = 0.f;

  const size_t base = ((size_t)b * S_ * H_ + h) * D_;
  const float* Qp = g_q + base;
  const float* Kp = g_k + base;
  const float* Vp = g_v + base;
  const float* Gp = g_gf + base;  // exp(g) precomputed
  const float* Bp = g_beta + (size_t)b * S_ * H_ + h;
  float* Op = g_attn + base;

  // prefetch t = 0 and stage it (threads 0..127 own the 128 channels)
  float kv = 0.f, qv = 0.f, gv = 0.f, vv = 0.f;
  float bt = Bp[0];
  if (tid < 128) {
    kv = Kp[tid]; qv = Qp[tid]; gv = Gp[tid]; vv = Vp[tid];
    stg[0][tid] = make_float4(kv, qv * SCALE_, gv, 0.f);
    vst[0][tid] = vv;
  }
  int buf = 0;
  __syncthreads();

  for (int t = 0; t < S_; t++) {
    float btc = bt;
    if (t + 1 < S_) {  // prefetch next step into regs (overlaps compute)
      bt = Bp[(size_t)(t + 1) * H_];
      if (tid < 128) {
        size_t o = (size_t)(t + 1) * HD_;
        kv = Kp[o + tid]; qv = Qp[o + tid]; gv = Gp[o + tid]; vv = Vp[o + tid];
      }
    }

    // phase 1: decay + k.S partial (warp-uniform broadcast reads), 16-deep slice
    const float4* st = stg[buf] + w * 16;
    float e = 0.f;
#pragma unroll
    for (int ii = 0; ii < 16; ii++) {
      float4 a = st[ii];
      float sv = Sacc[ii] * a.z;
      Sacc[ii] = sv;
      kk[ii] = a.x;
      qq[ii] = a.y;
      e += a.x * sv;
    }
    epart[l * 9 + w] = e;
    float vj = vst[buf][jcol];
    __syncthreads();

    const float* pe = epart + l * 9;
    float er = ((pe[0] + pe[1]) + (pe[2] + pe[3])) +
               ((pe[4] + pe[5]) + (pe[6] + pe[7]));
    float be = btc * (vj - er);

    // phase 2: rank-1 update + q.S partial (registers only)
    float o2 = 0.f;
#pragma unroll
    for (int ii = 0; ii < 16; ii++) {
      float sv = Sacc[ii] + kk[ii] * be;
      Sacc[ii] = sv;
      o2 += qq[ii] * sv;
    }
    opart[l * 9 + w] = o2;

    // stage t+1 while here
    if (tid < 128 && t + 1 < S_) {
      stg[buf ^ 1][tid] = make_float4(kv, qv * SCALE_, gv, 0.f);
      vst[buf ^ 1][tid] = vv;
    }
    __syncthreads();

    if (w == 0) {
      const float* po = opart + l * 9;
      float ov = ((po[0] + po[1]) + (po[2] + po[3])) +
                 ((po[4] + po[5]) + (po[6] + po[7]));
      Op[(size_t)t * HD_ + jcol] = ov;
    }
    buf ^= 1;
  }
}

// ---------------- RMSNorm * sigmoid gate -> bf16 hi/lo (fused split) ----------------
__global__ __launch_bounds__(128) void rmsgate_k(const float* __restrict__ rms_scale) {
  int row = blockIdx.x * 4 + (threadIdx.x >> 5);
  int lane = threadIdx.x & 31;
  const float* ap = g_attn + (size_t)row * 128;
  const float* gp = g_gate + (size_t)row * 128;
  float a0 = ap[lane], a1 = ap[lane + 32], a2 = ap[lane + 64], a3 = ap[lane + 96];
  float s = a0 * a0 + a1 * a1 + a2 * a2 + a3 * a3;
#pragma unroll
  for (int o = 16; o; o >>= 1) s += __shfl_xor_sync(0xffffffffu, s, o);
  float rn = rsqrtf(s * (1.f / 128.f) + 1e-5f);
#pragma unroll
  for (int j = 0; j < 4; j++) {
    int d = lane + 32 * j;
    float a = (j == 0) ? a0 : (j == 1) ? a1 : (j == 2) ? a2 : a3;
    float gt = gp[d];
    float o = a * rn * rms_scale[d] * (1.f / (1.f + __expf(-gt)));
    unsigned short hh, ll;
    split1(o, hh, ll);
    *reinterpret_cast<unsigned short*>(&g_noH[(size_t)row * 128 + d]) = hh;
    *reinterpret_cast<unsigned short*>(&g_noL[(size_t)row * 128 + d]) = ll;
  }
}

// ---------------- launch ----------------
extern "C" void kernel_launch(void* const* d_in, const int* in_sizes, int n_in,
                              void* d_out, int out_size) {
  const float* hs      = (const float*)d_in[0];
  const float* Wq      = (const float*)d_in[1];
  const float* Wk      = (const float*)d_in[2];
  const float* Wv      = (const float*)d_in[3];
  const float* conv_q  = (const float*)d_in[4];
  const float* conv_k  = (const float*)d_in[5];
  const float* conv_v  = (const float*)d_in[6];
  const float* Wb      = (const float*)d_in[7];
  const float* Wfa     = (const float*)d_in[8];
  const float* Wfb     = (const float*)d_in[9];
  const float* Wga     = (const float*)d_in[10];
  const float* Wgb     = (const float*)d_in[11];
  const float* A_log   = (const float*)d_in[12];
  const float* dt_bias = (const float*)d_in[13];
  const float* rmssc   = (const float*)d_in[14];
  const float* Wo      = (const float*)d_in[15];
  float* out = (float*)d_out;

  cudaFuncSetAttribute(gemm_tc, cudaFuncAttributeMaxDynamicSharedMemorySize, GSMEM_DYN);

  float *qkv, *gf, *gate, *qb, *kb, *vb;
  __nv_bfloat16 *hsH, *hsL, *WTh, *WTl, *fbTh, *fbTl, *gbTh, *gbTl, *WoTh, *WoTl;
  __nv_bfloat16 *fgaH, *fgaL, *noH, *noL;
  cudaGetSymbolAddress((void**)&qkv, g_qkv);
  cudaGetSymbolAddress((void**)&gf, g_gf);
  cudaGetSymbolAddress((void**)&gate, g_gate);
  cudaGetSymbolAddress((void**)&qb, g_q);
  cudaGetSymbolAddress((void**)&kb, g_k);
  cudaGetSymbolAddress((void**)&vb, g_v);
  cudaGetSymbolAddress((void**)&hsH, g_hsH);
  cudaGetSymbolAddress((void**)&hsL, g_hsL);
  cudaGetSymbolAddress((void**)&WTh, g_WTh);
  cudaGetSymbolAddress((void**)&WTl, g_WTl);
  cudaGetSymbolAddress((void**)&fbTh, g_fbTh);
  cudaGetSymbolAddress((void**)&fbTl, g_fbTl);
  cudaGetSymbolAddress((void**)&gbTh, g_gbTh);
  cudaGetSymbolAddress((void**)&gbTl, g_gbTl);
  cudaGetSymbolAddress((void**)&WoTh, g_WoTh);
  cudaGetSymbolAddress((void**)&WoTl, g_WoTl);
  cudaGetSymbolAddress((void**)&fgaH, g_fgaH);
  cudaGetSymbolAddress((void**)&fgaL, g_fgaL);
  cudaGetSymbolAddress((void**)&noH, g_noH);
  cudaGetSymbolAddress((void**)&noL, g_noL);

  const int nEl = M_ * HD_ / 256;

  // input conversions (A side) + weight transpose/split (B side)
  split4_k<<<M_ * HID_ / 4 / 256, 256>>>((const float4*)hs, hsH, hsL);
  wtrans_k<<<dim3(64, 64), 256>>>(Wq, WTh, WTl, 0, 2048, 2048);
  wtrans_k<<<dim3(64, 64), 256>>>(Wk, WTh, WTl, 2048, 2048, 2048);
  wtrans_k<<<dim3(64, 64), 256>>>(Wv, WTh, WTl, 4096, 2048, 2048);
  wtrans_k<<<dim3(4, 64), 256>>>(Wfa, WTh, WTl, 6144, 128, 2048);
  wtrans_k<<<dim3(4, 64), 256>>>(Wga, WTh, WTl, 6272, 128, 2048);
  wtrans_k<<<dim3(64, 4), 256>>>(Wfb, fbTh, fbTl, 0, 2048, 128);
  wtrans_k<<<dim3(64, 4), 256>>>(Wgb, gbTh, gbTl, 0, 2048, 128);
  wtrans_k<<<dim3(64, 64), 256>>>(Wo, WoTh, WoTl, 0, 2048, 2048);
  beta_k<<<M_, 128>>>(hs, Wb);

  // fused QKV + fa + ga projection: [4096,2048] @ [2048,6400]
  gemm_tc<<<dim3(100, 32), 256, GSMEM_DYN>>>(hsH, hsL, 2048, WTh, WTl, 2048, qkv, NQKV_, 2048);

  // forget/output gate projections (K=128)
  split_fga_k<<<M_ * 64 / 256, 256>>>();
  gemm_tc<<<dim3(32, 32), 256, GSMEM_DYN>>>(fgaH, fgaL, 256, fbTh, fbTl, 128, gf, 2048, 128);
  gemm_tc<<<dim3(32, 32), 256, GSMEM_DYN>>>(fgaH + 128, fgaL + 128, 256, gbTh, gbTl, 128, gate, 2048, 128);
  gsp_k<<<nEl, 256>>>(A_log, dt_bias);

  // l2norm on q,k; conv+silu on q,k,v
  l2q_k<<<32768, 128>>>();
  conv2_k<<<nEl, 256>>>(qkv + 0, conv_q, qb);
  conv2_k<<<nEl, 256>>>(qkv + 2048, conv_k, kb);
  conv2_k<<<nEl, 256>>>(qkv + 4096, conv_v, vb);

  // delta-rule scan (8-warp variant)
  delta_k<<<dim3(B_ * H_, 4), 256>>>();

  // rmsnorm*sigmoid gate (fused bf16 split), output projection
  rmsgate_k<<<M_ * H_ / 4, 128>>>(rmssc);
  gemm_tc<<<dim3(32, 32), 256, GSMEM_DYN>>>(noH, noL, 2048, WoTh, WoTl, 2048, out, 2048, 2048);
}

// round 14
// speedup vs baseline: 1.3753x; 1.2253x over previous
#include <cuda_runtime.h>
#include <cuda_bf16.h>
#include <math.h>
#include <stdint.h>

#define B_    2
#define S_    2048
#define HID_  2048
#define H_    16
#define D_    128
#define HD_   2048
#define M_    4096
#define NQKV_ 6400
#define SCALE_ 0.08838834764831845f  // D^-0.5

// ---------------- scratch (device globals; no allocation allowed) ----------------
__device__ __align__(256) float g_qkv[M_ * NQKV_];  // q|k|v|fa|ga packed cols
__device__ __align__(256) float g_gf[M_ * HD_];     // raw glin from gate GEMM
__device__ __align__(256) float g_gate[M_ * HD_];
__device__ __align__(256) float g_attn[M_ * HD_];
__device__ __align__(256) float g_beta[M_ * H_];
__device__ __align__(256) float4 g_pack[32 * S_ * 128];  // [bh][t][d] = {k, q*sc, exp(g), v}

__device__ __align__(256) __nv_bfloat16 g_hsH[M_ * HID_];
__device__ __align__(256) __nv_bfloat16 g_hsL[M_ * HID_];
__device__ __align__(256) __nv_bfloat16 g_WTh[NQKV_ * HID_];  // [Wq|Wk|Wv|Wfa|Wga]^T
__device__ __align__(256) __nv_bfloat16 g_WTl[NQKV_ * HID_];
__device__ __align__(256) __nv_bfloat16 g_fbTh[HD_ * D_];
__device__ __align__(256) __nv_bfloat16 g_fbTl[HD_ * D_];
__device__ __align__(256) __nv_bfloat16 g_gbTh[HD_ * D_];
__device__ __align__(256) __nv_bfloat16 g_gbTl[HD_ * D_];
__device__ __align__(256) __nv_bfloat16 g_WoTh[HID_ * HD_];
__device__ __align__(256) __nv_bfloat16 g_WoTl[HID_ * HD_];
__device__ __align__(256) __nv_bfloat16 g_fgaH[M_ * 256];
__device__ __align__(256) __nv_bfloat16 g_fgaL[M_ * 256];
__device__ __align__(256) __nv_bfloat16 g_noH[M_ * HD_];
__device__ __align__(256) __nv_bfloat16 g_noL[M_ * HD_];

// ---------------- PTX helpers (portable: sm_80+ features only) ----------------
__device__ __forceinline__ uint32_t s2u(const void* p) {
  uint32_t a;
  asm("{ .reg .u64 t; cvta.to.shared.u64 t, %1; cvt.u32.u64 %0, t; }" : "=r"(a) : "l"(p));
  return a;
}
__device__ __forceinline__ void cpa16(uint32_t d, const void* s) {
  asm volatile("cp.async.cg.shared.global [%0], [%1], 16;" :: "r"(d), "l"(s));
}
__device__ __forceinline__ void cpa_commit() { asm volatile("cp.async.commit_group;" ::: "memory"); }
template <int N> __device__ __forceinline__ void cpa_wait() {
  asm volatile("cp.async.wait_group %0;" :: "n"(N) : "memory");
}
__device__ __forceinline__ void ldm4(uint32_t* r, uint32_t a) {
  asm volatile("ldmatrix.sync.aligned.m8n8.x4.shared.b16 {%0,%1,%2,%3}, [%4];"
               : "=r"(r[0]), "=r"(r[1]), "=r"(r[2]), "=r"(r[3]) : "r"(a));
}
__device__ __forceinline__ void mma16816(float* d, const uint32_t* a, const uint32_t* b) {
  asm volatile(
      "mma.sync.aligned.m16n8k16.row.col.f32.bf16.bf16.f32 "
      "{%0,%1,%2,%3}, {%4,%5,%6,%7}, {%8,%9}, {%0,%1,%2,%3};"
      : "+f"(d[0]), "+f"(d[1]), "+f"(d[2]), "+f"(d[3])
      : "r"(a[0]), "r"(a[1]), "r"(a[2]), "r"(a[3]), "r"(b[0]), "r"(b[1]));
}

// ---------------- split-bf16 tensor-core GEMM (measured-best R5 config) ----------------
// C[M,N] = Ahi*Bhi + Ahi*Blo + Alo*Bhi. A:[M,K] K-major bf16, B:[N,K] K-major bf16.
// CTA tile 128x64, BK=32, 8 warps (4x2) each 32x32, 4-stage cp.async, 2 CTAs/SM.
#define GSTAGES 4
#define ATB 8192                // A tile: 128 rows x 64 bytes
#define BTB 4096                // B tile: 64 rows x 64 bytes
#define STB (2 * ATB + 2 * BTB) // Ah|Al|Bh|Bl per stage = 24KB
#define GSMEM_DYN (GSTAGES * STB)  // 96KB

__global__ __launch_bounds__(256, 2) void gemm_tc(
    const __nv_bfloat16* __restrict__ Ah, const __nv_bfloat16* __restrict__ Al, int lda,
    const __nv_bfloat16* __restrict__ Bh, const __nv_bfloat16* __restrict__ Bl, int ldb,
    float* __restrict__ C, int ldc, int K) {
  extern __shared__ __align__(16) char dsm[];
  const uint32_t sb = s2u(dsm);
  const int tid = threadIdx.x;
  const int lane = tid & 31, wid = tid >> 5;
  const int wm = wid >> 1, wn = wid & 1;
  const int m0 = blockIdx.y * 128, n0 = blockIdx.x * 64;
  const int NC = K >> 5;

  float acc[32];
#pragma unroll
  for (int i = 0; i < 32; i++) acc[i] = 0.f;

  auto ld_chunk = [&](int c, int stg) {
    const uint32_t tb = sb + stg * STB;
    const int kb = c * 32;
#pragma unroll
    for (int i = 0; i < 2; i++) {
      const int idx = tid + i * 256;
      const int row = idx >> 2, unit = idx & 3;
      const uint32_t so = (uint32_t)row * 64 + (uint32_t)((unit ^ ((row >> 1) & 3)) << 4);
      const size_t ao = (size_t)(m0 + row) * lda + kb + unit * 8;
      cpa16(tb + so, Ah + ao);
      cpa16(tb + ATB + so, Al + ao);
    }
    {
      const int row = tid >> 2, unit = tid & 3;
      const uint32_t so = (uint32_t)row * 64 + (uint32_t)((unit ^ ((row >> 1) & 3)) << 4);
      const size_t bo = (size_t)(n0 + row) * ldb + kb + unit * 8;
      cpa16(tb + 2 * ATB + so, Bh + bo);
      cpa16(tb + 2 * ATB + BTB + so, Bl + bo);
    }
  };

  for (int s = 0; s < GSTAGES && s < NC; s++) { ld_chunk(s, s); cpa_commit(); }

  for (int c = 0; c < NC; c++) {
    cpa_wait<3>();
    __syncthreads();
    const uint32_t tb = sb + (c & 3) * STB;
#pragma unroll
    for (int kk = 0; kk < 2; kk++) {
      const uint32_t aun = (uint32_t)(((kk * 2 + (lane >> 4)) ^ ((lane >> 1) & 3)) << 4);
      const uint32_t aaddr = tb + (uint32_t)(wm * 32 + (lane & 15)) * 64 + aun;
      const uint32_t bun = (uint32_t)(((kk * 2 + ((lane >> 3) & 1)) ^ ((lane >> 1) & 3)) << 4);
      const uint32_t baddr = tb + 2 * ATB +
          (uint32_t)(wn * 32 + ((lane >> 4) & 1) * 8 + (lane & 7)) * 64 + bun;

      uint32_t af[8], bhf[8], blf[8];
      ldm4(af, aaddr);
      ldm4(af + 4, aaddr + 1024);
      ldm4(bhf, baddr);
      ldm4(bhf + 4, baddr + 1024);
      ldm4(blf, baddr + BTB);
      ldm4(blf + 4, baddr + BTB + 1024);
#pragma unroll
      for (int mt = 0; mt < 2; mt++)
#pragma unroll
        for (int nt = 0; nt < 4; nt++)
          mma16816(&acc[(mt * 4 + nt) * 4], af + mt * 4, bhf + nt * 2);
#pragma unroll
      for (int mt = 0; mt < 2; mt++)
#pragma unroll
        for (int nt = 0; nt < 4; nt++)
          mma16816(&acc[(mt * 4 + nt) * 4], af + mt * 4, blf + nt * 2);
      // A-lo reuses A-hi registers
      ldm4(af, aaddr + ATB);
      ldm4(af + 4, aaddr + ATB + 1024);
#pragma unroll
      for (int mt = 0; mt < 2; mt++)
#pragma unroll
        for (int nt = 0; nt < 4; nt++)
          mma16816(&acc[(mt * 4 + nt) * 4], af + mt * 4, bhf + nt * 2);
    }
    if (c + 3 < NC) { ld_chunk(c + 3, (c + 3) & 3); cpa_commit(); }
  }

  const int rbase = m0 + wm * 32 + (lane >> 2);
  const int cbase = n0 + wn * 32 + (lane & 3) * 2;
#pragma unroll
  for (int mt = 0; mt < 2; mt++) {
#pragma unroll
    for (int nt = 0; nt < 4; nt++) {
      const float* a4 = &acc[(mt * 4 + nt) * 4];
      *(float2*)(C + (size_t)(rbase + mt * 16) * ldc + cbase + nt * 8) =
          make_float2(a4[0], a4[1]);
      *(float2*)(C + (size_t)(rbase + mt * 16 + 8) * ldc + cbase + nt * 8) =
          make_float2(a4[2], a4[3]);
    }
  }
}

// ---------------- fp32 -> bf16 hi/lo split ----------------
__device__ __forceinline__ void split1(float x, unsigned short& h, unsigned short& l) {
  __nv_bfloat16 hb = __float2bfloat16_rn(x);
  float r = x - __bfloat162float(hb);
  __nv_bfloat16 lb = __float2bfloat16_rn(r);
  h = *reinterpret_cast<unsigned short*>(&hb);
  l = *reinterpret_cast<unsigned short*>(&lb);
}

__global__ void split4_k(const float4* __restrict__ src, __nv_bfloat16* __restrict__ dh,
                         __nv_bfloat16* __restrict__ dl) {
  int i = blockIdx.x * blockDim.x + threadIdx.x;
  float4 v = src[i];
  ushort4 h, l;
  split1(v.x, h.x, l.x);
  split1(v.y, h.y, l.y);
  split1(v.z, h.z, l.z);
  split1(v.w, h.w, l.w);
  ((ushort4*)dh)[i] = h;
  ((ushort4*)dl)[i] = l;
}

__global__ void split_fga_k() {  // cols [6144,6400) of g_qkv -> compact [4096,256]
  int i = blockIdx.x * blockDim.x + threadIdx.x;  // over 4096*64
  int row = i >> 6, c4 = i & 63;
  float4 v = *(const float4*)&g_qkv[(size_t)row * NQKV_ + 6144 + c4 * 4];
  ushort4 h, l;
  split1(v.x, h.x, l.x);
  split1(v.y, h.y, l.y);
  split1(v.z, h.z, l.z);
  split1(v.w, h.w, l.w);
  *(ushort4*)&g_fgaH[(size_t)row * 256 + c4 * 4] = h;
  *(ushort4*)&g_fgaL[(size_t)row * 256 + c4 * 4] = l;
}

// ---------------- weight transpose + split: W[K,Nsrc] -> T[n_off+n][k] ----------------
__global__ __launch_bounds__(256) void wtrans_k(const float* __restrict__ src,
                                                __nv_bfloat16* __restrict__ dh,
                                                __nv_bfloat16* __restrict__ dl,
                                                int n_off, int Nsrc, int Kd) {
  __shared__ float t[32][33];
  int tx = threadIdx.x & 31, ty = threadIdx.x >> 5;
  int n0 = blockIdx.x * 32, k0 = blockIdx.y * 32;
#pragma unroll
  for (int i = 0; i < 4; i++) {
    int k = k0 + ty + i * 8;
    t[ty + i * 8][tx] = src[(size_t)k * Nsrc + n0 + tx];
  }
  __syncthreads();
#pragma unroll
  for (int i = 0; i < 4; i++) {
    int n = n0 + ty + i * 8;
    float v = t[tx][ty + i * 8];
    unsigned short h, l;
    split1(v, h, l);
    size_t o = (size_t)(n_off + n) * Kd + k0 + tx;
    *reinterpret_cast<unsigned short*>(&dh[o]) = h;
    *reinterpret_cast<unsigned short*>(&dl[o]) = l;
  }
}

// ---------------- l2 norm over q,k parts of g_qkv (cols [0,4096), groups of 128) ----------------
__global__ __launch_bounds__(128) void l2q_k() {
  int g = blockIdx.x * 4 + (threadIdx.x >> 5);
  int lane = threadIdx.x & 31;
  int row = g >> 5, cg = g & 31;
  float* p = g_qkv + (size_t)row * NQKV_ + cg * 128;
  float v0 = p[lane], v1 = p[lane + 32], v2 = p[lane + 64], v3 = p[lane + 96];
  float s = v0 * v0 + v1 * v1 + v2 * v2 + v3 * v3;
#pragma unroll
  for (int o = 16; o; o >>= 1) s += __shfl_xor_sync(0xffffffffu, s, o);
  float r = rsqrtf(s + 1e-6f);
  p[lane] = v0 * r;
  p[lane + 32] = v1 * r;
  p[lane + 64] = v2 * r;
  p[lane + 96] = v3 * r;
}

// ---------------- fused conv+SiLU (q,k,v) + softplus forget gate -> packed float4 ----------------
// One thread per (bs, c): coalesced float4 stores {k, q*sc, exp(g), v}.
__global__ void pack_k(const float* __restrict__ wq, const float* __restrict__ wk,
                       const float* __restrict__ wv, const float* __restrict__ A_log,
                       const float* __restrict__ dt_bias) {
  int idx = blockIdx.x * blockDim.x + threadIdx.x;
  int c = idx & (HD_ - 1);
  int bs = idx >> 11;
  int s = bs & (S_ - 1);
  int b = idx >> 22;
  int h = c >> 7, d = c & 127;

  const float* base = g_qkv + (size_t)(bs - 3) * NQKV_ + c;
  float aq = 0.f, ak = 0.f, av = 0.f;
#pragma unroll
  for (int j = 0; j < 4; j++) {
    if (s - 3 + j >= 0) {
      const float* r = base + (size_t)j * NQKV_;
      aq += r[0] * wq[j * HD_ + c];
      ak += r[2048] * wk[j * HD_ + c];
      av += r[4096] * wv[j * HD_ + c];
    }
  }
  float qc = aq / (1.f + __expf(-aq));
  float kc = ak / (1.f + __expf(-ak));
  float vc = av / (1.f + __expf(-av));

  float x = g_gf[idx] + dt_bias[c];
  float sp = (x > 20.f) ? x : log1pf(__expf(x));
  float ge = __expf(-expf(A_log[h]) * sp);

  g_pack[((((size_t)b * 16 + h) * S_ + s) * 128) + d] =
      make_float4(kc, qc * SCALE_, ge, vc);
}

// ---------------- beta = sigmoid(hs @ Wb), N=16 ----------------
__global__ __launch_bounds__(128) void beta_k(const float* __restrict__ hs,
                                              const float* __restrict__ Wb) {
  __shared__ float part[16][128];
  int m = blockIdx.x, tid = threadIdx.x;
  float acc[16];
#pragma unroll
  for (int h = 0; h < 16; h++) acc[h] = 0.f;
  const float* hp = hs + (size_t)m * HID_;
  for (int d = tid; d < HID_; d += 128) {
    float hv = hp[d];
    const float* wr = Wb + (size_t)d * 16;
#pragma unroll
    for (int h = 0; h < 16; h++) acc[h] += hv * wr[h];
  }
#pragma unroll
  for (int h = 0; h < 16; h++) part[h][tid] = acc[h];
  __syncthreads();
  for (int o = 64; o > 0; o >>= 1) {
    if (tid < o) {
#pragma unroll
      for (int h = 0; h < 16; h++) part[h][tid] += part[h][tid + o];
    }
    __syncthreads();
  }
  if (tid < 16) {
    float x = part[tid][0];
    g_beta[(size_t)m * 16 + tid] = 1.f / (1.f + __expf(-x));
  }
}

// ---------------- delta rule scan (warp = k-slice; broadcast LDS) — best-measured structure ----------------
// grid (32, 4): x = b*16+h, y = col group (32 cols). 128 thr = 4 warps (k-slices) x 32 lanes (cols).
__global__ __launch_bounds__(128) void delta_k() {
  const int bh = blockIdx.x;
  const int b = bh >> 4, h = bh & 15;
  const int grp = blockIdx.y;
  const int tid = threadIdx.x;
  const int w = tid >> 5;    // k-slice [32w, 32w+32)
  const int l = tid & 31;    // column within group
  const int jcol = grp * 32 + l;

  __shared__ float4 stg[2][128];   // element d: {k, q*sc, exp(g), v}
  __shared__ float vst[2][128];
  __shared__ float epart[160];     // [l*5 + w]
  __shared__ float opart[160];

  float Sacc[32], kk[32], qq[32];
#pragma unroll
  for (int i = 0; i < 32; i++) Sacc[i] = 0.f;

  const float4* Pp = g_pack + (size_t)bh * S_ * 128;
  const float* Bp = g_beta + (size_t)b * S_ * H_ + h;
  float* Op = g_attn + ((size_t)b * S_ * H_ + h) * D_;

  // prefetch t = 0 and stage it
  float4 pf = Pp[tid];
  float bt = Bp[0];
  stg[0][tid] = pf;
  vst[0][tid] = pf.w;
  int buf = 0;
  __syncthreads();

  for (int t = 0; t < S_; t++) {
    float btc = bt;
    if (t + 1 < S_) {  // prefetch next step into regs (overlaps compute)
      pf = Pp[(size_t)(t + 1) * 128 + tid];
      bt = Bp[(size_t)(t + 1) * H_];
    }

    // phase 1: decay + k.S partial (warp-uniform broadcast reads)
    const float4* st = stg[buf] + w * 32;
    float e = 0.f;
#pragma unroll
    for (int ii = 0; ii < 32; ii++) {
      float4 a = st[ii];
      float sv = Sacc[ii] * a.z;
      Sacc[ii] = sv;
      kk[ii] = a.x;
      qq[ii] = a.y;
      e += a.x * sv;
    }
    epart[l * 5 + w] = e;
    float vj = vst[buf][jcol];
    __syncthreads();

    float er = (epart[l * 5 + 0] + epart[l * 5 + 1]) +
               (epart[l * 5 + 2] + epart[l * 5 + 3]);
    float be = btc * (vj - er);

    // phase 2: rank-1 update + q.S partial (no LDS: k,q cached)
    float o2 = 0.f;
#pragma unroll
    for (int ii = 0; ii < 32; ii++) {
      float sv = Sacc[ii] + kk[ii] * be;
      Sacc[ii] = sv;
      o2 += qq[ii] * sv;
    }
    opart[l * 5 + w] = o2;

    // stage t+1 while here
    stg[buf ^ 1][tid] = pf;
    vst[buf ^ 1][tid] = pf.w;
    __syncthreads();

    if (w == 0) {
      float ov = (opart[l * 5 + 0] + opart[l * 5 + 1]) +
                 (opart[l * 5 + 2] + opart[l * 5 + 3]);
      Op[(size_t)t * HD_ + jcol] = ov;
    }
    buf ^= 1;
  }
}

// ---------------- RMSNorm * sigmoid gate -> bf16 hi/lo (fused split) ----------------
__global__ __launch_bounds__(128) void rmsgate_k(const float* __restrict__ rms_scale) {
  int row = blockIdx.x * 4 + (threadIdx.x >> 5);
  int lane = threadIdx.x & 31;
  const float* ap = g_attn + (size_t)row * 128;
  const float* gp = g_gate + (size_t)row * 128;
  float a0 = ap[lane], a1 = ap[lane + 32], a2 = ap[lane + 64], a3 = ap[lane + 96];
  float s = a0 * a0 + a1 * a1 + a2 * a2 + a3 * a3;
#pragma unroll
  for (int o = 16; o; o >>= 1) s += __shfl_xor_sync(0xffffffffu, s, o);
  float rn = rsqrtf(s * (1.f / 128.f) + 1e-5f);
#pragma unroll
  for (int j = 0; j < 4; j++) {
    int d = lane + 32 * j;
    float a = (j == 0) ? a0 : (j == 1) ? a1 : (j == 2) ? a2 : a3;
    float gt = gp[d];
    float o = a * rn * rms_scale[d] * (1.f / (1.f + __expf(-gt)));
    unsigned short hh, ll;
    split1(o, hh, ll);
    *reinterpret_cast<unsigned short*>(&g_noH[(size_t)row * 128 + d]) = hh;
    *reinterpret_cast<unsigned short*>(&g_noL[(size_t)row * 128 + d]) = ll;
  }
}

// ---------------- launch ----------------
extern "C" void kernel_launch(void* const* d_in, const int* in_sizes, int n_in,
                              void* d_out, int out_size) {
  const float* hs      = (const float*)d_in[0];
  const float* Wq      = (const float*)d_in[1];
  const float* Wk      = (const float*)d_in[2];
  const float* Wv      = (const float*)d_in[3];
  const float* conv_q  = (const float*)d_in[4];
  const float* conv_k  = (const float*)d_in[5];
  const float* conv_v  = (const float*)d_in[6];
  const float* Wb      = (const float*)d_in[7];
  const float* Wfa     = (const float*)d_in[8];
  const float* Wfb     = (const float*)d_in[9];
  const float* Wga     = (const float*)d_in[10];
  const float* Wgb     = (const float*)d_in[11];
  const float* A_log   = (const float*)d_in[12];
  const float* dt_bias = (const float*)d_in[13];
  const float* rmssc   = (const float*)d_in[14];
  const float* Wo      = (const float*)d_in[15];
  float* out = (float*)d_out;

  cudaFuncSetAttribute(gemm_tc, cudaFuncAttributeMaxDynamicSharedMemorySize, GSMEM_DYN);

  float *qkv, *gf, *gate;
  __nv_bfloat16 *hsH, *hsL, *WTh, *WTl, *fbTh, *fbTl, *gbTh, *gbTl, *WoTh, *WoTl;
  __nv_bfloat16 *fgaH, *fgaL, *noH, *noL;
  cudaGetSymbolAddress((void**)&qkv, g_qkv);
  cudaGetSymbolAddress((void**)&gf, g_gf);
  cudaGetSymbolAddress((void**)&gate, g_gate);
  cudaGetSymbolAddress((void**)&hsH, g_hsH);
  cudaGetSymbolAddress((void**)&hsL, g_hsL);
  cudaGetSymbolAddress((void**)&WTh, g_WTh);
  cudaGetSymbolAddress((void**)&WTl, g_WTl);
  cudaGetSymbolAddress((void**)&fbTh, g_fbTh);
  cudaGetSymbolAddress((void**)&fbTl, g_fbTl);
  cudaGetSymbolAddress((void**)&gbTh, g_gbTh);
  cudaGetSymbolAddress((void**)&gbTl, g_gbTl);
  cudaGetSymbolAddress((void**)&WoTh, g_WoTh);
  cudaGetSymbolAddress((void**)&WoTl, g_WoTl);
  cudaGetSymbolAddress((void**)&fgaH, g_fgaH);
  cudaGetSymbolAddress((void**)&fgaL, g_fgaL);
  cudaGetSymbolAddress((void**)&noH, g_noH);
  cudaGetSymbolAddress((void**)&noL, g_noL);

  const int nEl = M_ * HD_ / 256;

  // input conversions (A side) + weight transpose/split (B side)
  split4_k<<<M_ * HID_ / 4 / 256, 256>>>((const float4*)hs, hsH, hsL);
  wtrans_k<<<dim3(64, 64), 256>>>(Wq, WTh, WTl, 0, 2048, 2048);
  wtrans_k<<<dim3(64, 64), 256>>>(Wk, WTh, WTl, 2048, 2048, 2048);
  wtrans_k<<<dim3(64, 64), 256>>>(Wv, WTh, WTl, 4096, 2048, 2048);
  wtrans_k<<<dim3(4, 64), 256>>>(Wfa, WTh, WTl, 6144, 128, 2048);
  wtrans_k<<<dim3(4, 64), 256>>>(Wga, WTh, WTl, 6272, 128, 2048);
  wtrans_k<<<dim3(64, 4), 256>>>(Wfb, fbTh, fbTl, 0, 2048, 128);
  wtrans_k<<<dim3(64, 4), 256>>>(Wgb, gbTh, gbTl, 0, 2048, 128);
  wtrans_k<<<dim3(64, 64), 256>>>(Wo, WoTh, WoTl, 0, 2048, 2048);
  beta_k<<<M_, 128>>>(hs, Wb);

  // fused QKV + fa + ga projection: [4096,2048] @ [2048,6400]
  gemm_tc<<<dim3(100, 32), 256, GSMEM_DYN>>>(hsH, hsL, 2048, WTh, WTl, 2048, qkv, NQKV_, 2048);

  // forget/output gate projections (K=128); g_gf holds raw glin (pack_k applies softplus)
  split_fga_k<<<M_ * 64 / 256, 256>>>();
  gemm_tc<<<dim3(32, 32), 256, GSMEM_DYN>>>(fgaH, fgaL, 256, fbTh, fbTl, 128, gf, 2048, 128);
  gemm_tc<<<dim3(32, 32), 256, GSMEM_DYN>>>(fgaH + 128, fgaL + 128, 256, gbTh, gbTl, 128, gate, 2048, 128);

  // l2norm on q,k; fused conv+silu+gate -> packed staging
  l2q_k<<<32768, 128>>>();
  pack_k<<<nEl, 256>>>(conv_q, conv_k, conv_v, A_log, dt_bias);

  // delta-rule scan
  delta_k<<<dim3(B_ * H_, 4), 128>>>();

  // rmsnorm*sigmoid gate (fused bf16 split), output projection
  rmsgate_k<<<M_ * H_ / 4, 128>>>(rmssc);
  gemm_tc<<<dim3(32, 32), 256, GSMEM_DYN>>>(noH, noL, 2048, WoTh, WoTl, 2048, out, 2048, 2048);
}

// round 15
// speedup vs baseline: 1.5608x; 1.1349x over previous
#include <cuda_runtime.h>
#include <cuda_fp16.h>
#include <math.h>
#include <stdint.h>

#define B_    2
#define S_    2048
#define HID_  2048
#define H_    16
#define D_    128
#define HD_   2048
#define M_    4096
#define NQKV_ 6400
#define SCALE_ 0.08838834764831845f  // D^-0.5

// ---------------- scratch (device globals; no allocation allowed) ----------------
__device__ __align__(256) float g_qkv[M_ * NQKV_];  // q|k|v|fa|ga packed cols
__device__ __align__(256) float g_gf[M_ * HD_];     // raw glin from gate GEMM
__device__ __align__(256) float g_gate[M_ * HD_];
__device__ __align__(256) float g_attn[M_ * HD_];
__device__ __align__(256) float g_beta[M_ * H_];
__device__ __align__(256) float4 g_pack[32 * S_ * 128];  // [bh][t][d] = {k, q*sc, exp(g), v}

__device__ __align__(256) __half g_hsH[M_ * HID_];
__device__ __align__(256) __half g_hsL[M_ * HID_];
__device__ __align__(256) __half g_WT[NQKV_ * HID_];   // [Wq|Wk|Wv|Wfa|Wga]^T fp16
__device__ __align__(256) __half g_fbT[HD_ * D_];
__device__ __align__(256) __half g_gbT[HD_ * D_];
__device__ __align__(256) __half g_WoT[HID_ * HD_];
__device__ __align__(256) __half g_fgaH[M_ * 256];
__device__ __align__(256) __half g_fgaL[M_ * 256];
__device__ __align__(256) __half g_noH[M_ * HD_];
__device__ __align__(256) __half g_noL[M_ * HD_];

// ---------------- PTX helpers (portable: sm_80+ features only) ----------------
__device__ __forceinline__ uint32_t s2u(const void* p) {
  uint32_t a;
  asm("{ .reg .u64 t; cvta.to.shared.u64 t, %1; cvt.u32.u64 %0, t; }" : "=r"(a) : "l"(p));
  return a;
}
__device__ __forceinline__ void cpa16(uint32_t d, const void* s) {
  asm volatile("cp.async.cg.shared.global [%0], [%1], 16;" :: "r"(d), "l"(s));
}
__device__ __forceinline__ void cpa_commit() { asm volatile("cp.async.commit_group;" ::: "memory"); }
template <int N> __device__ __forceinline__ void cpa_wait() {
  asm volatile("cp.async.wait_group %0;" :: "n"(N) : "memory");
}
__device__ __forceinline__ void ldm4(uint32_t* r, uint32_t a) {
  asm volatile("ldmatrix.sync.aligned.m8n8.x4.shared.b16 {%0,%1,%2,%3}, [%4];"
               : "=r"(r[0]), "=r"(r[1]), "=r"(r[2]), "=r"(r[3]) : "r"(a));
}
__device__ __forceinline__ void mma16816(float* d, const uint32_t* a, const uint32_t* b) {
  asm volatile(
      "mma.sync.aligned.m16n8k16.row.col.f32.f16.f16.f32 "
      "{%0,%1,%2,%3}, {%4,%5,%6,%7}, {%8,%9}, {%0,%1,%2,%3};"
      : "+f"(d[0]), "+f"(d[1]), "+f"(d[2]), "+f"(d[3])
      : "r"(a[0]), "r"(a[1]), "r"(a[2]), "r"(a[3]), "r"(b[0]), "r"(b[1]));
}

// ---------------- split-fp16 tensor-core GEMM (2-pass: AhB + AlB) ----------------
// C[M,N] = (Ahi + Alo) * B. A:[M,K] K-major fp16 hi/lo, B:[N,K] K-major fp16.
// CTA tile 128x64, BK=32, 8 warps (4x2) each 32x32, 4-stage cp.async, 2 CTAs/SM.
#define GSTAGES 4
#define ATB 8192                // A tile: 128 rows x 64 bytes
#define BTB 4096                // B tile: 64 rows x 64 bytes
#define STB (2 * ATB + BTB)     // Ah|Al|B per stage = 20KB
#define GSMEM_DYN (GSTAGES * STB)  // 80KB

__global__ __launch_bounds__(256, 2) void gemm_tc(
    const __half* __restrict__ Ah, const __half* __restrict__ Al, int lda,
    const __half* __restrict__ Bm, int ldb,
    float* __restrict__ C, int ldc, int K) {
  extern __shared__ __align__(16) char dsm[];
  const uint32_t sb = s2u(dsm);
  const int tid = threadIdx.x;
  const int lane = tid & 31, wid = tid >> 5;
  const int wm = wid >> 1, wn = wid & 1;
  const int m0 = blockIdx.y * 128, n0 = blockIdx.x * 64;
  const int NC = K >> 5;

  float acc[32];
#pragma unroll
  for (int i = 0; i < 32; i++) acc[i] = 0.f;

  auto ld_chunk = [&](int c, int stg) {
    const uint32_t tb = sb + stg * STB;
    const int kb = c * 32;
#pragma unroll
    for (int i = 0; i < 2; i++) {
      const int idx = tid + i * 256;
      const int row = idx >> 2, unit = idx & 3;
      const uint32_t so = (uint32_t)row * 64 + (uint32_t)((unit ^ ((row >> 1) & 3)) << 4);
      const size_t ao = (size_t)(m0 + row) * lda + kb + unit * 8;
      cpa16(tb + so, Ah + ao);
      cpa16(tb + ATB + so, Al + ao);
    }
    {
      const int row = tid >> 2, unit = tid & 3;
      const uint32_t so = (uint32_t)row * 64 + (uint32_t)((unit ^ ((row >> 1) & 3)) << 4);
      const size_t bo = (size_t)(n0 + row) * ldb + kb + unit * 8;
      cpa16(tb + 2 * ATB + so, Bm + bo);
    }
  };

  for (int s = 0; s < GSTAGES && s < NC; s++) { ld_chunk(s, s); cpa_commit(); }

  for (int c = 0; c < NC; c++) {
    cpa_wait<3>();
    __syncthreads();
    const uint32_t tb = sb + (c & 3) * STB;
#pragma unroll
    for (int kk = 0; kk < 2; kk++) {
      const uint32_t aun = (uint32_t)(((kk * 2 + (lane >> 4)) ^ ((lane >> 1) & 3)) << 4);
      const uint32_t aaddr = tb + (uint32_t)(wm * 32 + (lane & 15)) * 64 + aun;
      const uint32_t bun = (uint32_t)(((kk * 2 + ((lane >> 3) & 1)) ^ ((lane >> 1) & 3)) << 4);
      const uint32_t baddr = tb + 2 * ATB +
          (uint32_t)(wn * 32 + ((lane >> 4) & 1) * 8 + (lane & 7)) * 64 + bun;

      uint32_t af[8], bf[8];
      ldm4(af, aaddr);
      ldm4(af + 4, aaddr + 1024);
      ldm4(bf, baddr);
      ldm4(bf + 4, baddr + 1024);
#pragma unroll
      for (int mt = 0; mt < 2; mt++)
#pragma unroll
        for (int nt = 0; nt < 4; nt++)
          mma16816(&acc[(mt * 4 + nt) * 4], af + mt * 4, bf + nt * 2);
      // A-lo pass reuses A-hi registers
      ldm4(af, aaddr + ATB);
      ldm4(af + 4, aaddr + ATB + 1024);
#pragma unroll
      for (int mt = 0; mt < 2; mt++)
#pragma unroll
        for (int nt = 0; nt < 4; nt++)
          mma16816(&acc[(mt * 4 + nt) * 4], af + mt * 4, bf + nt * 2);
    }
    if (c + 3 < NC) { ld_chunk(c + 3, (c + 3) & 3); cpa_commit(); }
  }

  const int rbase = m0 + wm * 32 + (lane >> 2);
  const int cbase = n0 + wn * 32 + (lane & 3) * 2;
#pragma unroll
  for (int mt = 0; mt < 2; mt++) {
#pragma unroll
    for (int nt = 0; nt < 4; nt++) {
      const float* a4 = &acc[(mt * 4 + nt) * 4];
      *(float2*)(C + (size_t)(rbase + mt * 16) * ldc + cbase + nt * 8) =
          make_float2(a4[0], a4[1]);
      *(float2*)(C + (size_t)(rbase + mt * 16 + 8) * ldc + cbase + nt * 8) =
          make_float2(a4[2], a4[3]);
    }
  }
}

// ---------------- fp32 -> fp16 hi/lo split ----------------
__device__ __forceinline__ void split1(float x, unsigned short& h, unsigned short& l) {
  __half hb = __float2half_rn(x);
  float r = x - __half2float(hb);
  __half lb = __float2half_rn(r);
  h = *reinterpret_cast<unsigned short*>(&hb);
  l = *reinterpret_cast<unsigned short*>(&lb);
}

__global__ void split4_k(const float4* __restrict__ src, __half* __restrict__ dh,
                         __half* __restrict__ dl) {
  int i = blockIdx.x * blockDim.x + threadIdx.x;
  float4 v = src[i];
  ushort4 h, l;
  split1(v.x, h.x, l.x);
  split1(v.y, h.y, l.y);
  split1(v.z, h.z, l.z);
  split1(v.w, h.w, l.w);
  ((ushort4*)dh)[i] = h;
  ((ushort4*)dl)[i] = l;
}

__global__ void split_fga_k() {  // cols [6144,6400) of g_qkv -> compact [4096,256]
  int i = blockIdx.x * blockDim.x + threadIdx.x;  // over 4096*64
  int row = i >> 6, c4 = i & 63;
  float4 v = *(const float4*)&g_qkv[(size_t)row * NQKV_ + 6144 + c4 * 4];
  ushort4 h, l;
  split1(v.x, h.x, l.x);
  split1(v.y, h.y, l.y);
  split1(v.z, h.z, l.z);
  split1(v.w, h.w, l.w);
  *(ushort4*)&g_fgaH[(size_t)row * 256 + c4 * 4] = h;
  *(ushort4*)&g_fgaL[(size_t)row * 256 + c4 * 4] = l;
}

// ---------------- weight transpose to fp16: W[K,Nsrc] -> T[n_off+n][k] ----------------
__global__ __launch_bounds__(256) void wtrans_k(const float* __restrict__ src,
                                                __half* __restrict__ dh,
                                                int n_off, int Nsrc, int Kd) {
  __shared__ float t[32][33];
  int tx = threadIdx.x & 31, ty = threadIdx.x >> 5;
  int n0 = blockIdx.x * 32, k0 = blockIdx.y * 32;
#pragma unroll
  for (int i = 0; i < 4; i++) {
    int k = k0 + ty + i * 8;
    t[ty + i * 8][tx] = src[(size_t)k * Nsrc + n0 + tx];
  }
  __syncthreads();
#pragma unroll
  for (int i = 0; i < 4; i++) {
    int n = n0 + ty + i * 8;
    dh[(size_t)(n_off + n) * Kd + k0 + tx] = __float2half_rn(t[tx][ty + i * 8]);
  }
}

// ---------------- l2 norm over q,k parts of g_qkv (cols [0,4096), groups of 128) ----------------
__global__ __launch_bounds__(128) void l2q_k() {
  int g = blockIdx.x * 4 + (threadIdx.x >> 5);
  int lane = threadIdx.x & 31;
  int row = g >> 5, cg = g & 31;
  float* p = g_qkv + (size_t)row * NQKV_ + cg * 128;
  float v0 = p[lane], v1 = p[lane + 32], v2 = p[lane + 64], v3 = p[lane + 96];
  float s = v0 * v0 + v1 * v1 + v2 * v2 + v3 * v3;
#pragma unroll
  for (int o = 16; o; o >>= 1) s += __shfl_xor_sync(0xffffffffu, s, o);
  float r = rsqrtf(s + 1e-6f);
  p[lane] = v0 * r;
  p[lane + 32] = v1 * r;
  p[lane + 64] = v2 * r;
  p[lane + 96] = v3 * r;
}

// ---------------- fused conv+SiLU (q,k,v) + softplus forget gate -> packed float4 ----------------
__global__ void pack_k(const float* __restrict__ wq, const float* __restrict__ wk,
                       const float* __restrict__ wv, const float* __restrict__ A_log,
                       const float* __restrict__ dt_bias) {
  int idx = blockIdx.x * blockDim.x + threadIdx.x;
  int c = idx & (HD_ - 1);
  int bs = idx >> 11;
  int s = bs & (S_ - 1);
  int b = idx >> 22;
  int h = c >> 7, d = c & 127;

  const float* base = g_qkv + (size_t)(bs - 3) * NQKV_ + c;
  float aq = 0.f, ak = 0.f, av = 0.f;
#pragma unroll
  for (int j = 0; j < 4; j++) {
    if (s - 3 + j >= 0) {
      const float* r = base + (size_t)j * NQKV_;
      aq += r[0] * wq[j * HD_ + c];
      ak += r[2048] * wk[j * HD_ + c];
      av += r[4096] * wv[j * HD_ + c];
    }
  }
  float qc = aq / (1.f + __expf(-aq));
  float kc = ak / (1.f + __expf(-ak));
  float vc = av / (1.f + __expf(-av));

  float x = g_gf[idx] + dt_bias[c];
  float sp = (x > 20.f) ? x : log1pf(__expf(x));
  float ge = __expf(-expf(A_log[h]) * sp);

  g_pack[((((size_t)b * 16 + h) * S_ + s) * 128) + d] =
      make_float4(kc, qc * SCALE_, ge, vc);
}

// ---------------- beta = sigmoid(hs @ Wb), N=16 ----------------
__global__ __launch_bounds__(128) void beta_k(const float* __restrict__ hs,
                                              const float* __restrict__ Wb) {
  __shared__ float part[16][128];
  int m = blockIdx.x, tid = threadIdx.x;
  float acc[16];
#pragma unroll
  for (int h = 0; h < 16; h++) acc[h] = 0.f;
  const float* hp = hs + (size_t)m * HID_;
  for (int d = tid; d < HID_; d += 128) {
    float hv = hp[d];
    const float* wr = Wb + (size_t)d * 16;
#pragma unroll
    for (int h = 0; h < 16; h++) acc[h] += hv * wr[h];
  }
#pragma unroll
  for (int h = 0; h < 16; h++) part[h][tid] = acc[h];
  __syncthreads();
  for (int o = 64; o > 0; o >>= 1) {
    if (tid < o) {
#pragma unroll
      for (int h = 0; h < 16; h++) part[h][tid] += part[h][tid + o];
    }
    __syncthreads();
  }
  if (tid < 16) {
    float x = part[tid][0];
    g_beta[(size_t)m * 16 + tid] = 1.f / (1.f + __expf(-x));
  }
}

// ---------------- delta rule scan (warp = k-slice; broadcast LDS) — best-measured structure ----------------
__global__ __launch_bounds__(128) void delta_k() {
  const int bh = blockIdx.x;
  const int b = bh >> 4, h = bh & 15;
  const int grp = blockIdx.y;
  const int tid = threadIdx.x;
  const int w = tid >> 5;    // k-slice [32w, 32w+32)
  const int l = tid & 31;    // column within group
  const int jcol = grp * 32 + l;

  __shared__ float4 stg[2][128];   // element d: {k, q*sc, exp(g), v}
  __shared__ float vst[2][128];
  __shared__ float epart[160];     // [l*5 + w]
  __shared__ float opart[160];

  float Sacc[32], kk[32], qq[32];
#pragma unroll
  for (int i = 0; i < 32; i++) Sacc[i] = 0.f;

  const float4* Pp = g_pack + (size_t)bh * S_ * 128;
  const float* Bp = g_beta + (size_t)b * S_ * H_ + h;
  float* Op = g_attn + ((size_t)b * S_ * H_ + h) * D_;

  float4 pf = Pp[tid];
  float bt = Bp[0];
  stg[0][tid] = pf;
  vst[0][tid] = pf.w;
  int buf = 0;
  __syncthreads();

  for (int t = 0; t < S_; t++) {
    float btc = bt;
    if (t + 1 < S_) {
      pf = Pp[(size_t)(t + 1) * 128 + tid];
      bt = Bp[(size_t)(t + 1) * H_];
    }

    const float4* st = stg[buf] + w * 32;
    float e = 0.f;
#pragma unroll
    for (int ii = 0; ii < 32; ii++) {
      float4 a = st[ii];
      float sv = Sacc[ii] * a.z;
      Sacc[ii] = sv;
      kk[ii] = a.x;
      qq[ii] = a.y;
      e += a.x * sv;
    }
    epart[l * 5 + w] = e;
    float vj = vst[buf][jcol];
    __syncthreads();

    float er = (epart[l * 5 + 0] + epart[l * 5 + 1]) +
               (epart[l * 5 + 2] + epart[l * 5 + 3]);
    float be = btc * (vj - er);

    float o2 = 0.f;
#pragma unroll
    for (int ii = 0; ii < 32; ii++) {
      float sv = Sacc[ii] + kk[ii] * be;
      Sacc[ii] = sv;
      o2 += qq[ii] * sv;
    }
    opart[l * 5 + w] = o2;

    stg[buf ^ 1][tid] = pf;
    vst[buf ^ 1][tid] = pf.w;
    __syncthreads();

    if (w == 0) {
      float ov = (opart[l * 5 + 0] + opart[l * 5 + 1]) +
                 (opart[l * 5 + 2] + opart[l * 5 + 3]);
      Op[(size_t)t * HD_ + jcol] = ov;
    }
    buf ^= 1;
  }
}

// ---------------- RMSNorm * sigmoid gate -> fp16 hi/lo (fused split) ----------------
__global__ __launch_bounds__(128) void rmsgate_k(const float* __restrict__ rms_scale) {
  int row = blockIdx.x * 4 + (threadIdx.x >> 5);
  int lane = threadIdx.x & 31;
  const float* ap = g_attn + (size_t)row * 128;
  const float* gp = g_gate + (size_t)row * 128;
  float a0 = ap[lane], a1 = ap[lane + 32], a2 = ap[lane + 64], a3 = ap[lane + 96];
  float s = a0 * a0 + a1 * a1 + a2 * a2 + a3 * a3;
#pragma unroll
  for (int o = 16; o; o >>= 1) s += __shfl_xor_sync(0xffffffffu, s, o);
  float rn = rsqrtf(s * (1.f / 128.f) + 1e-5f);
#pragma unroll
  for (int j = 0; j < 4; j++) {
    int d = lane + 32 * j;
    float a = (j == 0) ? a0 : (j == 1) ? a1 : (j == 2) ? a2 : a3;
    float gt = gp[d];
    float o = a * rn * rms_scale[d] * (1.f / (1.f + __expf(-gt)));
    unsigned short hh, ll;
    split1(o, hh, ll);
    *reinterpret_cast<unsigned short*>(&g_noH[(size_t)row * 128 + d]) = hh;
    *reinterpret_cast<unsigned short*>(&g_noL[(size_t)row * 128 + d]) = ll;
  }
}

// ---------------- launch ----------------
extern "C" void kernel_launch(void* const* d_in, const int* in_sizes, int n_in,
                              void* d_out, int out_size) {
  const float* hs      = (const float*)d_in[0];
  const float* Wq      = (const float*)d_in[1];
  const float* Wk      = (const float*)d_in[2];
  const float* Wv      = (const float*)d_in[3];
  const float* conv_q  = (const float*)d_in[4];
  const float* conv_k  = (const float*)d_in[5];
  const float* conv_v  = (const float*)d_in[6];
  const float* Wb      = (const float*)d_in[7];
  const float* Wfa     = (const float*)d_in[8];
  const float* Wfb     = (const float*)d_in[9];
  const float* Wga     = (const float*)d_in[10];
  const float* Wgb     = (const float*)d_in[11];
  const float* A_log   = (const float*)d_in[12];
  const float* dt_bias = (const float*)d_in[13];
  const float* rmssc   = (const float*)d_in[14];
  const float* Wo      = (const float*)d_in[15];
  float* out = (float*)d_out;

  cudaFuncSetAttribute(gemm_tc, cudaFuncAttributeMaxDynamicSharedMemorySize, GSMEM_DYN);

  float *qkv, *gf, *gate;
  __half *hsH, *hsL, *WT, *fbT, *gbT, *WoT, *fgaH, *fgaL, *noH, *noL;
  cudaGetSymbolAddress((void**)&qkv, g_qkv);
  cudaGetSymbolAddress((void**)&gf, g_gf);
  cudaGetSymbolAddress((void**)&gate, g_gate);
  cudaGetSymbolAddress((void**)&hsH, g_hsH);
  cudaGetSymbolAddress((void**)&hsL, g_hsL);
  cudaGetSymbolAddress((void**)&WT, g_WT);
  cudaGetSymbolAddress((void**)&fbT, g_fbT);
  cudaGetSymbolAddress((void**)&gbT, g_gbT);
  cudaGetSymbolAddress((void**)&WoT, g_WoT);
  cudaGetSymbolAddress((void**)&fgaH, g_fgaH);
  cudaGetSymbolAddress((void**)&fgaL, g_fgaL);
  cudaGetSymbolAddress((void**)&noH, g_noH);
  cudaGetSymbolAddress((void**)&noL, g_noL);

  const int nEl = M_ * HD_ / 256;

  // input conversions (A side) + weight transpose (B side, fp16)
  split4_k<<<M_ * HID_ / 4 / 256, 256>>>((const float4*)hs, hsH, hsL);
  wtrans_k<<<dim3(64, 64), 256>>>(Wq, WT, 0, 2048, 2048);
  wtrans_k<<<dim3(64, 64), 256>>>(Wk, WT, 2048, 2048, 2048);
  wtrans_k<<<dim3(64, 64), 256>>>(Wv, WT, 4096, 2048, 2048);
  wtrans_k<<<dim3(4, 64), 256>>>(Wfa, WT, 6144, 128, 2048);
  wtrans_k<<<dim3(4, 64), 256>>>(Wga, WT, 6272, 128, 2048);
  wtrans_k<<<dim3(64, 4), 256>>>(Wfb, fbT, 0, 2048, 128);
  wtrans_k<<<dim3(64, 4), 256>>>(Wgb, gbT, 0, 2048, 128);
  wtrans_k<<<dim3(64, 64), 256>>>(Wo, WoT, 0, 2048, 2048);
  beta_k<<<M_, 128>>>(hs, Wb);

  // fused QKV + fa + ga projection: [4096,2048] @ [2048,6400]
  gemm_tc<<<dim3(100, 32), 256, GSMEM_DYN>>>(hsH, hsL, 2048, WT, 2048, qkv, NQKV_, 2048);

  // forget/output gate projections (K=128); g_gf holds raw glin (pack_k applies softplus)
  split_fga_k<<<M_ * 64 / 256, 256>>>();
  gemm_tc<<<dim3(32, 32), 256, GSMEM_DYN>>>(fgaH, fgaL, 256, fbT, 128, gf, 2048, 128);
  gemm_tc<<<dim3(32, 32), 256, GSMEM_DYN>>>(fgaH + 128, fgaL + 128, 256, gbT, 128, gate, 2048, 128);

  // l2norm on q,k; fused conv+silu+gate -> packed staging
  l2q_k<<<32768, 128>>>();
  pack_k<<<nEl, 256>>>(conv_q, conv_k, conv_v, A_log, dt_bias);

  // delta-rule scan
  delta_k<<<dim3(B_ * H_, 4), 128>>>();

  // rmsnorm*sigmoid gate (fused fp16 split), output projection
  rmsgate_k<<<M_ * H_ / 4, 128>>>(rmssc);
  gemm_tc<<<dim3(32, 32), 256, GSMEM_DYN>>>(noH, noL, 2048, WoT, 2048, out, 2048, 2048);
}